// round 1
// baseline (speedup 1.0000x reference)
#include <cuda_runtime.h>
#include <cstdint>
#include <cstddef>

#define NND 50000
#define NED 800000
#define F0 1433
#define F1 256
#define F2 32
#define F3 7

// ---------------- device scratch (static allocation is allowed) -------------
__device__ float g_csrc[NND];
__device__ float g_cdst[NND];
__device__ float g_h1[(size_t)NND * F1];
__device__ float g_agg1[(size_t)NND * F1];
__device__ float g_x1[(size_t)NND * F1];
__device__ float g_h2[(size_t)NND * F2];
__device__ float g_agg2[(size_t)NND * F2];
__device__ float g_x2[(size_t)NND * F2];
__device__ float g_h3[(size_t)NND * 8];
__device__ float g_agg3[(size_t)NND * 8];
__device__ int   g_is64;

// ---------------- helpers ---------------------------------------------------
__device__ __forceinline__ void red_add4(float* p, float4 v) {
    asm volatile("red.global.add.v4.f32 [%0], {%1,%2,%3,%4};"
                 :: "l"(__cvta_generic_to_global(p)),
                    "f"(v.x), "f"(v.y), "f"(v.z), "f"(v.w) : "memory");
}
__device__ __forceinline__ void red_add1(float* p, float v) {
    asm volatile("red.global.add.f32 [%0], %1;"
                 :: "l"(__cvta_generic_to_global(p)), "f"(v) : "memory");
}
__device__ __forceinline__ int load_idx(const void* edge, int is64, long long lin) {
    if (is64) return (int)((const long long*)edge)[lin];
    return ((const int*)edge)[lin];
}

// ---------------- detect int64 vs int32 edge indices ------------------------
__global__ void detect_kernel(const void* edge) {
    if (threadIdx.x == 0 && blockIdx.x == 0) {
        const unsigned long long* p = (const unsigned long long*)edge;
        int ok = 1;
        #pragma unroll
        for (int i = 0; i < 16; i++)
            if (p[i] >= (unsigned long long)NND) ok = 0;
        g_is64 = ok;
    }
}

// ---------------- zero ------------------------------------------------------
__global__ void zero_kernel(float* p, long long n) {
    long long stride = (long long)gridDim.x * blockDim.x;
    for (long long i = (long long)blockIdx.x * blockDim.x + threadIdx.x; i < n; i += stride)
        p[i] = 0.f;
}

// ---------------- degree + norm --------------------------------------------
__global__ void deg_kernel(const void* edge) {
    int is64 = g_is64;
    int stride = gridDim.x * blockDim.x;
    for (int e = blockIdx.x * blockDim.x + threadIdx.x; e < NED; e += stride) {
        int s = load_idx(edge, is64, e);
        int d = load_idx(edge, is64, (long long)NED + e);
        atomicAdd(&g_csrc[s], 1.f);
        atomicAdd(&g_cdst[d], 1.f);
    }
}

__global__ void rsqrt_kernel() {
    int i = blockIdx.x * blockDim.x + threadIdx.x;
    if (i < NND)              g_csrc[i]       = rsqrtf(fmaxf(g_csrc[i], 1.f));
    else if (i < 2 * NND)     g_cdst[i - NND] = rsqrtf(fmaxf(g_cdst[i - NND], 1.f));
}

// ---------------- GEMM1: [50000,1433] @ [1433,256], epilogue * c_src --------
#define BM 128
#define BN 128
#define BK 16

__global__ __launch_bounds__(256, 2)
void gemm1_kernel(const float* __restrict__ A, const float* __restrict__ B,
                  float* __restrict__ C, const float* __restrict__ csrc) {
    __shared__ float As[BK][BM + 4];   // +4 pad: keeps float4 alignment, kills store conflicts
    __shared__ float Bs[BK][BN];

    const int tid = threadIdx.x;
    const int bm = blockIdx.x * BM;
    const int bn = blockIdx.y * BN;
    const int tr = (tid >> 4) << 3;    // 0..120 step 8
    const int tc = (tid & 15) << 3;

    const int a_r = tid >> 4;          // 0..15
    const int a_c = tid & 15;          // k within tile
    const int b_r = tid >> 5;          // 0..7
    const int b_c = (tid & 31) << 2;   // 0..124 step 4

    float acc[8][8];
    #pragma unroll
    for (int i = 0; i < 8; i++)
        #pragma unroll
        for (int j = 0; j < 8; j++) acc[i][j] = 0.f;

    for (int k0 = 0; k0 < F0; k0 += BK) {
        // A tile: scalar loads (rows of A are not 16B aligned, K=1433 odd)
        #pragma unroll
        for (int i = 0; i < 8; i++) {
            int row = bm + a_r + 16 * i;
            int col = k0 + a_c;
            float v = 0.f;
            if (row < NND && col < F0) v = A[(size_t)row * F0 + col];
            As[a_c][a_r + 16 * i] = v;
        }
        // B tile: float4 loads (rows of B are 256 floats, aligned)
        #pragma unroll
        for (int i = 0; i < 2; i++) {
            int row = k0 + b_r + 8 * i;
            float4 v = make_float4(0.f, 0.f, 0.f, 0.f);
            if (row < F0) v = *(const float4*)(B + (size_t)row * 256 + bn + b_c);
            *(float4*)&Bs[b_r + 8 * i][b_c] = v;
        }
        __syncthreads();
        #pragma unroll
        for (int kk = 0; kk < BK; kk++) {
            float4 a0 = *(const float4*)&As[kk][tr];
            float4 a1 = *(const float4*)&As[kk][tr + 4];
            float4 b0 = *(const float4*)&Bs[kk][tc];
            float4 b1 = *(const float4*)&Bs[kk][tc + 4];
            float av[8] = {a0.x, a0.y, a0.z, a0.w, a1.x, a1.y, a1.z, a1.w};
            float bv[8] = {b0.x, b0.y, b0.z, b0.w, b1.x, b1.y, b1.z, b1.w};
            #pragma unroll
            for (int i = 0; i < 8; i++)
                #pragma unroll
                for (int j = 0; j < 8; j++)
                    acc[i][j] = fmaf(av[i], bv[j], acc[i][j]);
        }
        __syncthreads();
    }
    #pragma unroll
    for (int i = 0; i < 8; i++) {
        int row = bm + tr + i;
        if (row < NND) {
            float s = csrc[row];
            float4 o0 = make_float4(acc[i][0] * s, acc[i][1] * s, acc[i][2] * s, acc[i][3] * s);
            float4 o1 = make_float4(acc[i][4] * s, acc[i][5] * s, acc[i][6] * s, acc[i][7] * s);
            *(float4*)(C + (size_t)row * 256 + bn + tc)     = o0;
            *(float4*)(C + (size_t)row * 256 + bn + tc + 4) = o1;
        }
    }
}

// ---------------- edge scatter: agg[dst] += h[src] (F = 4<<LOGF4 floats) ----
template <int LOGF4>
__global__ void scatter_kernel(const float* __restrict__ h, float* __restrict__ agg,
                               const void* __restrict__ edge) {
    const int F4 = 1 << LOGF4;
    int is64 = g_is64;
    long long total  = (long long)NED << LOGF4;
    long long stride = (long long)gridDim.x * blockDim.x;
    for (long long t = (long long)blockIdx.x * blockDim.x + threadIdx.x; t < total; t += stride) {
        int e = (int)(t >> LOGF4);
        int k = (int)t & (F4 - 1);
        int s = load_idx(edge, is64, e);
        int d = load_idx(edge, is64, (long long)NED + e);
        float4 v = *(const float4*)(h + ((size_t)s << (LOGF4 + 2)) + 4 * k);
        red_add4(agg + ((size_t)d << (LOGF4 + 2)) + 4 * k, v);
    }
}

// scalar scatter for the 7-wide final layer (stride-8 storage)
__global__ void scatter7_kernel(const float* __restrict__ h, float* __restrict__ agg,
                                const void* __restrict__ edge) {
    int is64 = g_is64;
    long long total  = (long long)NED * 8;
    long long stride = (long long)gridDim.x * blockDim.x;
    for (long long t = (long long)blockIdx.x * blockDim.x + threadIdx.x; t < total; t += stride) {
        int e = (int)(t >> 3);
        int k = (int)t & 7;
        if (k < 7) {
            int s = load_idx(edge, is64, e);
            int d = load_idx(edge, is64, (long long)NED + e);
            red_add1(agg + (size_t)d * 8 + k, h[(size_t)s * 8 + k]);
        }
    }
}

// ---------------- post: relu(agg * c_dst + b) -------------------------------
__global__ void post1_kernel(const float* __restrict__ agg, const float* __restrict__ b,
                             const float* __restrict__ cdst, float* __restrict__ out) {
    long long n = (long long)NND * 256;
    long long stride = (long long)gridDim.x * blockDim.x;
    for (long long i = (long long)blockIdx.x * blockDim.x + threadIdx.x; i < n; i += stride) {
        int m = (int)(i >> 8);
        out[i] = fmaxf(fmaf(agg[i], cdst[m], b[(int)i & 255]), 0.f);
    }
}
__global__ void post2_kernel(const float* __restrict__ agg, const float* __restrict__ b,
                             const float* __restrict__ cdst, float* __restrict__ out) {
    long long n = (long long)NND * 32;
    long long stride = (long long)gridDim.x * blockDim.x;
    for (long long i = (long long)blockIdx.x * blockDim.x + threadIdx.x; i < n; i += stride) {
        int m = (int)(i >> 5);
        out[i] = fmaxf(fmaf(agg[i], cdst[m], b[(int)i & 31]), 0.f);
    }
}

// ---------------- GEMM2: [50000,256] @ [256,32], * c_src --------------------
__global__ __launch_bounds__(1024)
void gemm2_kernel(const float* __restrict__ x1, const float* __restrict__ W2,
                  float* __restrict__ h2, const float* __restrict__ csrc) {
    __shared__ float Ws[256 * 32];
    int tid = threadIdx.x;
    for (int i = tid; i < 256 * 32; i += 1024) Ws[i] = W2[i];
    __syncthreads();
    int m = blockIdx.x * 32 + (tid >> 5);
    int c = tid & 31;
    if (m >= NND) return;
    const float4* xr = (const float4*)(x1 + (size_t)m * 256);
    float acc = 0.f;
    #pragma unroll
    for (int k4 = 0; k4 < 64; k4++) {
        float4 x = xr[k4];
        int k = k4 * 4;
        acc = fmaf(x.x, Ws[(k + 0) * 32 + c], acc);
        acc = fmaf(x.y, Ws[(k + 1) * 32 + c], acc);
        acc = fmaf(x.z, Ws[(k + 2) * 32 + c], acc);
        acc = fmaf(x.w, Ws[(k + 3) * 32 + c], acc);
    }
    h2[(size_t)m * 32 + c] = acc * csrc[m];
}

// ---------------- GEMM3: [50000,32] @ [32,7], * c_src (stride-8 out) --------
__global__ void gemm3_kernel(const float* __restrict__ x2, const float* __restrict__ W3,
                             float* __restrict__ h3, const float* __restrict__ csrc) {
    __shared__ float Ws[32 * 7];
    int tid = threadIdx.x;
    if (tid < 224) Ws[tid] = W3[tid];
    __syncthreads();
    int m = blockIdx.x * blockDim.x + tid;
    if (m >= NND) return;
    const float4* xr = (const float4*)(x2 + (size_t)m * 32);
    float x[32];
    #pragma unroll
    for (int i = 0; i < 8; i++) {
        float4 v = xr[i];
        x[4 * i] = v.x; x[4 * i + 1] = v.y; x[4 * i + 2] = v.z; x[4 * i + 3] = v.w;
    }
    float s = csrc[m];
    #pragma unroll
    for (int j = 0; j < 7; j++) {
        float a = 0.f;
        #pragma unroll
        for (int k = 0; k < 32; k++) a = fmaf(x[k], Ws[k * 7 + j], a);
        h3[(size_t)m * 8 + j] = a * s;
    }
}

// ---------------- final: log_softmax(agg3 * c_dst + b3) ---------------------
__global__ void final_kernel(const float* __restrict__ agg3, const float* __restrict__ b3,
                             const float* __restrict__ cdst, float* __restrict__ out) {
    int m = blockIdx.x * blockDim.x + threadIdx.x;
    if (m >= NND) return;
    float c = cdst[m];
    float v[7];
    float mx = -1e30f;
    #pragma unroll
    for (int j = 0; j < 7; j++) {
        v[j] = fmaf(agg3[(size_t)m * 8 + j], c, b3[j]);
        mx = fmaxf(mx, v[j]);
    }
    float se = 0.f;
    #pragma unroll
    for (int j = 0; j < 7; j++) se += expf(v[j] - mx);
    float l = logf(se);
    #pragma unroll
    for (int j = 0; j < 7; j++) out[(size_t)m * 7 + j] = v[j] - mx - l;
}

// ---------------- host ------------------------------------------------------
extern "C" void kernel_launch(void* const* d_in, const int* in_sizes, int n_in,
                              void* d_out, int out_size) {
    const float* feat = (const float*)d_in[0];
    const void*  edge = d_in[1];
    const float* W1   = (const float*)d_in[2];
    const float* b1   = (const float*)d_in[3];
    const float* W2   = (const float*)d_in[4];
    const float* b2   = (const float*)d_in[5];
    const float* W3   = (const float*)d_in[6];
    const float* b3   = (const float*)d_in[7];
    float* out = (float*)d_out;

    float *p_csrc, *p_cdst, *p_h1, *p_agg1, *p_x1, *p_h2, *p_agg2, *p_x2, *p_h3, *p_agg3;
    cudaGetSymbolAddress((void**)&p_csrc, g_csrc);
    cudaGetSymbolAddress((void**)&p_cdst, g_cdst);
    cudaGetSymbolAddress((void**)&p_h1,   g_h1);
    cudaGetSymbolAddress((void**)&p_agg1, g_agg1);
    cudaGetSymbolAddress((void**)&p_x1,   g_x1);
    cudaGetSymbolAddress((void**)&p_h2,   g_h2);
    cudaGetSymbolAddress((void**)&p_agg2, g_agg2);
    cudaGetSymbolAddress((void**)&p_x2,   g_x2);
    cudaGetSymbolAddress((void**)&p_h3,   g_h3);
    cudaGetSymbolAddress((void**)&p_agg3, g_agg3);

    detect_kernel<<<1, 1>>>(edge);

    zero_kernel<<<128, 256>>>(p_csrc, NND);
    zero_kernel<<<128, 256>>>(p_cdst, NND);
    zero_kernel<<<4096, 256>>>(p_agg1, (long long)NND * 256);
    zero_kernel<<<1024, 256>>>(p_agg2, (long long)NND * 32);
    zero_kernel<<<512, 256>>>(p_agg3, (long long)NND * 8);

    deg_kernel<<<1024, 256>>>(edge);
    rsqrt_kernel<<<(2 * NND + 255) / 256, 256>>>();

    // Layer 1
    dim3 g1((NND + BM - 1) / BM, 256 / BN);
    gemm1_kernel<<<g1, 256>>>(feat, W1, p_h1, p_csrc);
    scatter_kernel<6><<<(int)(((long long)NED * 64 + 255) / 256), 256>>>(p_h1, p_agg1, edge);
    post1_kernel<<<8192, 256>>>(p_agg1, b1, p_cdst, p_x1);

    // Layer 2
    gemm2_kernel<<<(NND + 31) / 32, 1024>>>(p_x1, W2, p_h2, p_csrc);
    scatter_kernel<3><<<(int)(((long long)NED * 8 + 255) / 256), 256>>>(p_h2, p_agg2, edge);
    post2_kernel<<<2048, 256>>>(p_agg2, b2, p_cdst, p_x2);

    // Layer 3
    gemm3_kernel<<<(NND + 255) / 256, 256>>>(p_x2, W3, p_h3, p_csrc);
    scatter7_kernel<<<(int)(((long long)NED * 8 + 255) / 256), 256>>>(p_h3, p_agg3, edge);
    final_kernel<<<(NND + 255) / 256, 256>>>(p_agg3, b3, p_cdst, out);
}

// round 2
// speedup vs baseline: 1.4872x; 1.4872x over previous
#include <cuda_runtime.h>
#include <cuda_bf16.h>
#include <cstdint>
#include <cstddef>

#define NND 50000
#define NED 800000
#define F0 1433
#define KP 1440            // K padded to mult of 32
#define MP 50048           // M padded to mult of 64 (782*64)
#define F1 256
#define F2 32

// ---------------- device scratch (static allocation is allowed) -------------
__device__ float g_csrc[NND];
__device__ float g_cdst[NND];
__device__ float g_h1[(size_t)NND * F1];
__device__ float g_agg1[(size_t)NND * F1];
__device__ float g_x1[(size_t)NND * F1];
__device__ float g_h2[(size_t)NND * F2];
__device__ float g_agg2[(size_t)NND * F2];
__device__ float g_x2[(size_t)NND * F2];
__device__ float g_h3[(size_t)NND * 8];
__device__ float g_agg3[(size_t)NND * 8];
__device__ int   g_is64;
// bf16-split operands for GEMM1
__device__ __nv_bfloat16 g_Ah[(size_t)MP * KP];
__device__ __nv_bfloat16 g_Al[(size_t)MP * KP];
__device__ __nv_bfloat16 g_Bh[(size_t)KP * F1];
__device__ __nv_bfloat16 g_Bl[(size_t)KP * F1];

// ---------------- helpers ---------------------------------------------------
__device__ __forceinline__ void red_add4(float* p, float4 v) {
    asm volatile("red.global.add.v4.f32 [%0], {%1,%2,%3,%4};"
                 :: "l"(__cvta_generic_to_global(p)),
                    "f"(v.x), "f"(v.y), "f"(v.z), "f"(v.w) : "memory");
}
__device__ __forceinline__ void red_add1(float* p, float v) {
    asm volatile("red.global.add.f32 [%0], %1;"
                 :: "l"(__cvta_generic_to_global(p)), "f"(v) : "memory");
}
__device__ __forceinline__ int load_idx(const void* edge, int is64, long long lin) {
    if (is64) return (int)((const long long*)edge)[lin];
    return ((const int*)edge)[lin];
}
__device__ __forceinline__ void cpa16(uint32_t dst, const void* src) {
    asm volatile("cp.async.cg.shared.global [%0],[%1],16;" :: "r"(dst), "l"(src));
}
#define CP_COMMIT() asm volatile("cp.async.commit_group;")
#define CP_WAIT1()  asm volatile("cp.async.wait_group 1;")

__device__ __forceinline__ void ldsm4(uint32_t& r0, uint32_t& r1, uint32_t& r2, uint32_t& r3, uint32_t a) {
    asm volatile("ldmatrix.sync.aligned.m8n8.x4.shared.b16 {%0,%1,%2,%3},[%4];"
                 : "=r"(r0), "=r"(r1), "=r"(r2), "=r"(r3) : "r"(a));
}
__device__ __forceinline__ void ldsm4t(uint32_t& r0, uint32_t& r1, uint32_t& r2, uint32_t& r3, uint32_t a) {
    asm volatile("ldmatrix.sync.aligned.m8n8.x4.trans.shared.b16 {%0,%1,%2,%3},[%4];"
                 : "=r"(r0), "=r"(r1), "=r"(r2), "=r"(r3) : "r"(a));
}
__device__ __forceinline__ void mma16816(float* c, const uint32_t* a, uint32_t b0, uint32_t b1) {
    asm volatile("mma.sync.aligned.m16n8k16.row.col.f32.bf16.bf16.f32 "
                 "{%0,%1,%2,%3},{%4,%5,%6,%7},{%8,%9},{%0,%1,%2,%3};"
                 : "+f"(c[0]), "+f"(c[1]), "+f"(c[2]), "+f"(c[3])
                 : "r"(a[0]), "r"(a[1]), "r"(a[2]), "r"(a[3]), "r"(b0), "r"(b1));
}

// ---------------- detect int64 vs int32 edge indices ------------------------
__global__ void detect_kernel(const void* edge) {
    if (threadIdx.x == 0 && blockIdx.x == 0) {
        const unsigned long long* p = (const unsigned long long*)edge;
        int ok = 1;
        #pragma unroll
        for (int i = 0; i < 16; i++)
            if (p[i] >= (unsigned long long)NND) ok = 0;
        g_is64 = ok;
    }
}

// ---------------- zero ------------------------------------------------------
__global__ void zero_kernel(float* p, long long n) {
    long long stride = (long long)gridDim.x * blockDim.x;
    for (long long i = (long long)blockIdx.x * blockDim.x + threadIdx.x; i < n; i += stride)
        p[i] = 0.f;
}

// ---------------- degree + norm --------------------------------------------
__global__ void deg_kernel(const void* edge) {
    int is64 = g_is64;
    int stride = gridDim.x * blockDim.x;
    for (int e = blockIdx.x * blockDim.x + threadIdx.x; e < NED; e += stride) {
        int s = load_idx(edge, is64, e);
        int d = load_idx(edge, is64, (long long)NED + e);
        atomicAdd(&g_csrc[s], 1.f);
        atomicAdd(&g_cdst[d], 1.f);
    }
}

__global__ void rsqrt_kernel() {
    int i = blockIdx.x * blockDim.x + threadIdx.x;
    if (i < NND)              g_csrc[i]       = rsqrtf(fmaxf(g_csrc[i], 1.f));
    else if (i < 2 * NND)     g_cdst[i - NND] = rsqrtf(fmaxf(g_cdst[i - NND], 1.f));
}

// ---------------- bf16-split conversion -------------------------------------
__global__ void convA_kernel(const float* __restrict__ A) {
    long long total  = (long long)MP * (KP / 2);
    long long stride = (long long)gridDim.x * blockDim.x;
    for (long long i = (long long)blockIdx.x * blockDim.x + threadIdx.x; i < total; i += stride) {
        int row = (int)(i / (KP / 2));
        int c2  = (int)(i % (KP / 2)) * 2;
        float x0 = 0.f, x1 = 0.f;
        if (row < NND) {
            if (c2 < F0)     x0 = A[(size_t)row * F0 + c2];
            if (c2 + 1 < F0) x1 = A[(size_t)row * F0 + c2 + 1];
        }
        __nv_bfloat16 h0 = __float2bfloat16(x0);
        __nv_bfloat16 h1 = __float2bfloat16(x1);
        __nv_bfloat16 l0 = __float2bfloat16(x0 - __bfloat162float(h0));
        __nv_bfloat16 l1 = __float2bfloat16(x1 - __bfloat162float(h1));
        __nv_bfloat162 hh; hh.x = h0; hh.y = h1;
        __nv_bfloat162 ll; ll.x = l0; ll.y = l1;
        *(__nv_bfloat162*)&g_Ah[(size_t)row * KP + c2] = hh;
        *(__nv_bfloat162*)&g_Al[(size_t)row * KP + c2] = ll;
    }
}
__global__ void convB_kernel(const float* __restrict__ W1) {
    long long total  = (long long)KP * (F1 / 2);
    long long stride = (long long)gridDim.x * blockDim.x;
    for (long long i = (long long)blockIdx.x * blockDim.x + threadIdx.x; i < total; i += stride) {
        int k  = (int)(i / (F1 / 2));
        int c2 = (int)(i % (F1 / 2)) * 2;
        float x0 = 0.f, x1 = 0.f;
        if (k < F0) { x0 = W1[(size_t)k * F1 + c2]; x1 = W1[(size_t)k * F1 + c2 + 1]; }
        __nv_bfloat16 h0 = __float2bfloat16(x0);
        __nv_bfloat16 h1 = __float2bfloat16(x1);
        __nv_bfloat16 l0 = __float2bfloat16(x0 - __bfloat162float(h0));
        __nv_bfloat16 l1 = __float2bfloat16(x1 - __bfloat162float(h1));
        __nv_bfloat162 hh; hh.x = h0; hh.y = h1;
        __nv_bfloat162 ll; ll.x = l0; ll.y = l1;
        *(__nv_bfloat162*)&g_Bh[(size_t)k * F1 + c2] = hh;
        *(__nv_bfloat162*)&g_Bl[(size_t)k * F1 + c2] = ll;
    }
}

// ---------------- GEMM1: tensor-core bf16-split -----------------------------
// C[50000,256] = A[*,1433] @ W1 ; epilogue * c_src
// Block: 64(M) x 256(N) x 32(K-stage), 512 threads = 16 warps (2m x 8n), warp tile 32x32.
#define GBM 64
#define GBK 32
#define NT  (KP / GBK)         /* 45 */
#define ASTRB 80               /* A smem row stride bytes (40 bf16) */
#define BSTRB 528              /* B smem row stride bytes (264 bf16) */
#define SA_SZ 5120             /* 64*80 */
#define SB_SZ 16896            /* 32*528 */
#define SMEM_TOTAL_G1 (4*SA_SZ + 4*SB_SZ)   /* 88064 */

extern __shared__ char g1_smem[];

__global__ __launch_bounds__(512, 1)
void gemm1_mma(const __nv_bfloat16* __restrict__ Ah, const __nv_bfloat16* __restrict__ Al,
               const __nv_bfloat16* __restrict__ Bh, const __nv_bfloat16* __restrict__ Bl,
               float* __restrict__ C, const float* __restrict__ csrc)
{
    const int tid = threadIdx.x;
    const int l   = tid & 31;
    const int wid = tid >> 5;
    const int mw  = (wid & 1) * 32;
    const int nw  = (wid >> 1) * 32;
    const int bm  = blockIdx.x * GBM;

    const uint32_t sbase = (uint32_t)__cvta_generic_to_shared(g1_smem);
    // SA(buf,h) = sbase + (buf*2+h)*SA_SZ ; SB(buf,h) = sbase + 4*SA_SZ + (buf*2+h)*SB_SZ

    // per-thread prefetch geometry (1 A chunk + 4 B chunks of 16B each)
    const int a_row = tid >> 3, a_sub = tid & 7, a_h = a_sub >> 2, a_c = a_sub & 3;
    const __nv_bfloat16* a_srcbase = (a_h ? Al : Ah) + (size_t)(bm + a_row) * KP + a_c * 8;
    const uint32_t a_dstoff = (uint32_t)(a_row * ASTRB + a_c * 16 + a_h * SA_SZ);

    float acc[2][4][4];
    #pragma unroll
    for (int t = 0; t < 2; t++)
        #pragma unroll
        for (int j = 0; j < 4; j++)
            #pragma unroll
            for (int q = 0; q < 4; q++) acc[t][j][q] = 0.f;

    auto prefetch = [&](int kt, int buf) {
        cpa16(sbase + (uint32_t)(buf * 2 * SA_SZ) + a_dstoff, a_srcbase + kt * GBK);
        #pragma unroll
        for (int i = 0; i < 4; i++) {
            int cid = tid + 512 * i;
            int row = cid >> 6, sub = cid & 63, h = sub >> 5, c = sub & 31;
            const __nv_bfloat16* src = (h ? Bl : Bh) + (size_t)(kt * GBK + row) * F1 + c * 8;
            uint32_t dst = sbase + (uint32_t)(4 * SA_SZ + (buf * 2 + h) * SB_SZ + row * BSTRB + c * 16);
            cpa16(dst, src);
        }
    };

    prefetch(0, 0);
    CP_COMMIT();

    const int      lrow  = ((l >> 3) & 1) * 8 + (l & 7);
    const uint32_t acolb = (uint32_t)((l >> 4) * 16);
    const uint32_t bcolb = (uint32_t)((nw + ((l >> 4) ? 8 : 0)) * 2);

    for (int kt = 0; kt < NT; kt++) {
        if (kt + 1 < NT) prefetch(kt + 1, (kt + 1) & 1);
        CP_COMMIT();
        CP_WAIT1();
        __syncthreads();

        const int buf = kt & 1;
        const uint32_t sa0 = sbase + (uint32_t)(buf * 2 * SA_SZ);
        const uint32_t sa1 = sa0 + SA_SZ;
        const uint32_t sb0 = sbase + (uint32_t)(4 * SA_SZ + buf * 2 * SB_SZ);
        const uint32_t sb1 = sb0 + SB_SZ;

        #pragma unroll
        for (int ks = 0; ks < 2; ks++) {
            uint32_t ah[2][4], al_[2][4], bh[2][4], bl_[2][4];
            #pragma unroll
            for (int t = 0; t < 2; t++) {
                uint32_t off = (uint32_t)((mw + t * 16 + lrow) * ASTRB) + acolb + ks * 32;
                ldsm4(ah[t][0],  ah[t][1],  ah[t][2],  ah[t][3],  sa0 + off);
                ldsm4(al_[t][0], al_[t][1], al_[t][2], al_[t][3], sa1 + off);
            }
            const int brow = ks * 16 + lrow;
            #pragma unroll
            for (int g = 0; g < 2; g++) {
                uint32_t off = (uint32_t)(brow * BSTRB) + bcolb + (uint32_t)(g * 32);
                ldsm4t(bh[g][0],  bh[g][1],  bh[g][2],  bh[g][3],  sb0 + off);
                ldsm4t(bl_[g][0], bl_[g][1], bl_[g][2], bl_[g][3], sb1 + off);
            }
            #pragma unroll
            for (int t = 0; t < 2; t++)
                #pragma unroll
                for (int j = 0; j < 4; j++) {
                    uint32_t b0h = bh[j >> 1][(j & 1) * 2], b1h = bh[j >> 1][(j & 1) * 2 + 1];
                    uint32_t b0l = bl_[j >> 1][(j & 1) * 2], b1l = bl_[j >> 1][(j & 1) * 2 + 1];
                    mma16816(acc[t][j], ah[t],  b0h, b1h);
                    mma16816(acc[t][j], ah[t],  b0l, b1l);
                    mma16816(acc[t][j], al_[t], b0h, b1h);
                }
        }
        __syncthreads();
    }

    // epilogue: * csrc, store
    #pragma unroll
    for (int t = 0; t < 2; t++) {
        int r0 = bm + mw + t * 16 + (l >> 2);
        #pragma unroll
        for (int half = 0; half < 2; half++) {
            int row = r0 + half * 8;
            if (row < NND) {
                float s = csrc[row];
                #pragma unroll
                for (int j = 0; j < 4; j++) {
                    int col = nw + j * 8 + (l & 3) * 2;
                    float2 v;
                    v.x = acc[t][j][half * 2]     * s;
                    v.y = acc[t][j][half * 2 + 1] * s;
                    *(float2*)&C[(size_t)row * F1 + col] = v;
                }
            }
        }
    }
}

// ---------------- edge scatter: agg[dst] += h[src] (F = 4<<LOGF4 floats) ----
template <int LOGF4>
__global__ void scatter_kernel(const float* __restrict__ h, float* __restrict__ agg,
                               const void* __restrict__ edge) {
    const int F4 = 1 << LOGF4;
    int is64 = g_is64;
    long long total  = (long long)NED << LOGF4;
    long long stride = (long long)gridDim.x * blockDim.x;
    for (long long t = (long long)blockIdx.x * blockDim.x + threadIdx.x; t < total; t += stride) {
        int e = (int)(t >> LOGF4);
        int k = (int)t & (F4 - 1);
        int s = load_idx(edge, is64, e);
        int d = load_idx(edge, is64, (long long)NED + e);
        float4 v = *(const float4*)(h + ((size_t)s << (LOGF4 + 2)) + 4 * k);
        red_add4(agg + ((size_t)d << (LOGF4 + 2)) + 4 * k, v);
    }
}

__global__ void scatter7_kernel(const float* __restrict__ h, float* __restrict__ agg,
                                const void* __restrict__ edge) {
    int is64 = g_is64;
    long long total  = (long long)NED * 8;
    long long stride = (long long)gridDim.x * blockDim.x;
    for (long long t = (long long)blockIdx.x * blockDim.x + threadIdx.x; t < total; t += stride) {
        int e = (int)(t >> 3);
        int k = (int)t & 7;
        if (k < 7) {
            int s = load_idx(edge, is64, e);
            int d = load_idx(edge, is64, (long long)NED + e);
            red_add1(agg + (size_t)d * 8 + k, h[(size_t)s * 8 + k]);
        }
    }
}

// ---------------- post: relu(agg * c_dst + b) -------------------------------
__global__ void post1_kernel(const float* __restrict__ agg, const float* __restrict__ b,
                             const float* __restrict__ cdst, float* __restrict__ out) {
    long long n = (long long)NND * 256;
    long long stride = (long long)gridDim.x * blockDim.x;
    for (long long i = (long long)blockIdx.x * blockDim.x + threadIdx.x; i < n; i += stride) {
        int m = (int)(i >> 8);
        out[i] = fmaxf(fmaf(agg[i], cdst[m], b[(int)i & 255]), 0.f);
    }
}
__global__ void post2_kernel(const float* __restrict__ agg, const float* __restrict__ b,
                             const float* __restrict__ cdst, float* __restrict__ out) {
    long long n = (long long)NND * 32;
    long long stride = (long long)gridDim.x * blockDim.x;
    for (long long i = (long long)blockIdx.x * blockDim.x + threadIdx.x; i < n; i += stride) {
        int m = (int)(i >> 5);
        out[i] = fmaxf(fmaf(agg[i], cdst[m], b[(int)i & 31]), 0.f);
    }
}

// ---------------- GEMM2: [50000,256] @ [256,32], * c_src --------------------
__global__ __launch_bounds__(1024)
void gemm2_kernel(const float* __restrict__ x1, const float* __restrict__ W2,
                  float* __restrict__ h2, const float* __restrict__ csrc) {
    __shared__ float Ws[256 * 32];
    int tid = threadIdx.x;
    for (int i = tid; i < 256 * 32; i += 1024) Ws[i] = W2[i];
    __syncthreads();
    int m = blockIdx.x * 32 + (tid >> 5);
    int c = tid & 31;
    if (m >= NND) return;
    const float4* xr = (const float4*)(x1 + (size_t)m * 256);
    float acc = 0.f;
    #pragma unroll
    for (int k4 = 0; k4 < 64; k4++) {
        float4 x = xr[k4];
        int k = k4 * 4;
        acc = fmaf(x.x, Ws[(k + 0) * 32 + c], acc);
        acc = fmaf(x.y, Ws[(k + 1) * 32 + c], acc);
        acc = fmaf(x.z, Ws[(k + 2) * 32 + c], acc);
        acc = fmaf(x.w, Ws[(k + 3) * 32 + c], acc);
    }
    h2[(size_t)m * 32 + c] = acc * csrc[m];
}

// ---------------- GEMM3: [50000,32] @ [32,7], * c_src (stride-8 out) --------
__global__ void gemm3_kernel(const float* __restrict__ x2, const float* __restrict__ W3,
                             float* __restrict__ h3, const float* __restrict__ csrc) {
    __shared__ float Ws[32 * 7];
    int tid = threadIdx.x;
    if (tid < 224) Ws[tid] = W3[tid];
    __syncthreads();
    int m = blockIdx.x * blockDim.x + tid;
    if (m >= NND) return;
    const float4* xr = (const float4*)(x2 + (size_t)m * 32);
    float x[32];
    #pragma unroll
    for (int i = 0; i < 8; i++) {
        float4 v = xr[i];
        x[4 * i] = v.x; x[4 * i + 1] = v.y; x[4 * i + 2] = v.z; x[4 * i + 3] = v.w;
    }
    float s = csrc[m];
    #pragma unroll
    for (int j = 0; j < 7; j++) {
        float a = 0.f;
        #pragma unroll
        for (int k = 0; k < 32; k++) a = fmaf(x[k], Ws[k * 7 + j], a);
        h3[(size_t)m * 8 + j] = a * s;
    }
}

// ---------------- final: log_softmax(agg3 * c_dst + b3) ---------------------
__global__ void final_kernel(const float* __restrict__ agg3, const float* __restrict__ b3,
                             const float* __restrict__ cdst, float* __restrict__ out) {
    int m = blockIdx.x * blockDim.x + threadIdx.x;
    if (m >= NND) return;
    float c = cdst[m];
    float v[7];
    float mx = -1e30f;
    #pragma unroll
    for (int j = 0; j < 7; j++) {
        v[j] = fmaf(agg3[(size_t)m * 8 + j], c, b3[j]);
        mx = fmaxf(mx, v[j]);
    }
    float se = 0.f;
    #pragma unroll
    for (int j = 0; j < 7; j++) se += expf(v[j] - mx);
    float l = logf(se);
    #pragma unroll
    for (int j = 0; j < 7; j++) out[(size_t)m * 7 + j] = v[j] - mx - l;
}

// ---------------- host ------------------------------------------------------
extern "C" void kernel_launch(void* const* d_in, const int* in_sizes, int n_in,
                              void* d_out, int out_size) {
    const float* feat = (const float*)d_in[0];
    const void*  edge = d_in[1];
    const float* W1   = (const float*)d_in[2];
    const float* b1   = (const float*)d_in[3];
    const float* W2   = (const float*)d_in[4];
    const float* b2   = (const float*)d_in[5];
    const float* W3   = (const float*)d_in[6];
    const float* b3   = (const float*)d_in[7];
    float* out = (float*)d_out;

    float *p_csrc, *p_cdst, *p_h1, *p_agg1, *p_x1, *p_h2, *p_agg2, *p_x2, *p_h3, *p_agg3;
    __nv_bfloat16 *p_Ah, *p_Al, *p_Bh, *p_Bl;
    cudaGetSymbolAddress((void**)&p_csrc, g_csrc);
    cudaGetSymbolAddress((void**)&p_cdst, g_cdst);
    cudaGetSymbolAddress((void**)&p_h1,   g_h1);
    cudaGetSymbolAddress((void**)&p_agg1, g_agg1);
    cudaGetSymbolAddress((void**)&p_x1,   g_x1);
    cudaGetSymbolAddress((void**)&p_h2,   g_h2);
    cudaGetSymbolAddress((void**)&p_agg2, g_agg2);
    cudaGetSymbolAddress((void**)&p_x2,   g_x2);
    cudaGetSymbolAddress((void**)&p_h3,   g_h3);
    cudaGetSymbolAddress((void**)&p_agg3, g_agg3);
    cudaGetSymbolAddress((void**)&p_Ah,   g_Ah);
    cudaGetSymbolAddress((void**)&p_Al,   g_Al);
    cudaGetSymbolAddress((void**)&p_Bh,   g_Bh);
    cudaGetSymbolAddress((void**)&p_Bl,   g_Bl);

    static int smem_set = 0;
    if (!smem_set) {
        cudaFuncSetAttribute(gemm1_mma, cudaFuncAttributeMaxDynamicSharedMemorySize, SMEM_TOTAL_G1);
        smem_set = 1;
    }

    detect_kernel<<<1, 1>>>(edge);

    zero_kernel<<<128, 256>>>(p_csrc, NND);
    zero_kernel<<<128, 256>>>(p_cdst, NND);
    zero_kernel<<<4096, 256>>>(p_agg1, (long long)NND * 256);
    zero_kernel<<<1024, 256>>>(p_agg2, (long long)NND * 32);
    zero_kernel<<<512, 256>>>(p_agg3, (long long)NND * 8);

    convA_kernel<<<8192, 256>>>(feat);
    convB_kernel<<<256, 256>>>(W1);

    deg_kernel<<<1024, 256>>>(edge);
    rsqrt_kernel<<<(2 * NND + 255) / 256, 256>>>();

    // Layer 1 (tensor-core bf16-split GEMM)
    gemm1_mma<<<MP / GBM, 512, SMEM_TOTAL_G1>>>(p_Ah, p_Al, p_Bh, p_Bl, p_h1, p_csrc);
    scatter_kernel<6><<<(int)(((long long)NED * 64 + 255) / 256), 256>>>(p_h1, p_agg1, edge);
    post1_kernel<<<8192, 256>>>(p_agg1, b1, p_cdst, p_x1);

    // Layer 2
    gemm2_kernel<<<(NND + 31) / 32, 1024>>>(p_x1, W2, p_h2, p_csrc);
    scatter_kernel<3><<<(int)(((long long)NED * 8 + 255) / 256), 256>>>(p_h2, p_agg2, edge);
    post2_kernel<<<2048, 256>>>(p_agg2, b2, p_cdst, p_x2);

    // Layer 3
    gemm3_kernel<<<(NND + 255) / 256, 256>>>(p_x2, W3, p_h3, p_csrc);
    scatter7_kernel<<<(int)(((long long)NED * 8 + 255) / 256), 256>>>(p_h3, p_agg3, edge);
    final_kernel<<<(NND + 255) / 256, 256>>>(p_agg3, b3, p_cdst, out);
}

// round 3
// speedup vs baseline: 1.9900x; 1.3381x over previous
#include <cuda_runtime.h>
#include <cuda_bf16.h>
#include <cstdint>
#include <cstddef>

#define NND 50000
#define NED 800000
#define F0 1433
#define KP 1440            // K padded to mult of 32
#define MP 50048           // M padded to mult of 64
#define F1 256
#define F2 32

// ---------------- device scratch -------------------------------------------
__device__ float g_csrc[NND];
__device__ float g_cdst[NND];
__device__ float g_h1[(size_t)NND * F1];
__device__ float g_x1[(size_t)NND * F1];
__device__ float g_h2[(size_t)NND * F2];
__device__ float g_x2[(size_t)NND * F2];
__device__ float g_h3[(size_t)NND * 8];
__device__ int   g_is64;
__device__ int   g_degin[NND];
__device__ int   g_degout[NND];
__device__ int   g_off[NND + 1];
__device__ int   g_cur[NND];
__device__ int   g_srcl[NED];
// bf16-split W1
__device__ __nv_bfloat16 g_Bh[(size_t)KP * F1];
__device__ __nv_bfloat16 g_Bl[(size_t)KP * F1];

// ---------------- helpers ---------------------------------------------------
__device__ __forceinline__ int load_idx(const void* edge, int is64, long long lin) {
    if (is64) return (int)((const long long*)edge)[lin];
    return ((const int*)edge)[lin];
}
__device__ __forceinline__ void cpa16(uint32_t dst, const void* src) {
    asm volatile("cp.async.cg.shared.global [%0],[%1],16;" :: "r"(dst), "l"(src));
}
#define CP_COMMIT() asm volatile("cp.async.commit_group;")
#define CP_WAIT1()  asm volatile("cp.async.wait_group 1;")

__device__ __forceinline__ void ldsm4(uint32_t& r0, uint32_t& r1, uint32_t& r2, uint32_t& r3, uint32_t a) {
    asm volatile("ldmatrix.sync.aligned.m8n8.x4.shared.b16 {%0,%1,%2,%3},[%4];"
                 : "=r"(r0), "=r"(r1), "=r"(r2), "=r"(r3) : "r"(a));
}
__device__ __forceinline__ void ldsm4t(uint32_t& r0, uint32_t& r1, uint32_t& r2, uint32_t& r3, uint32_t a) {
    asm volatile("ldmatrix.sync.aligned.m8n8.x4.trans.shared.b16 {%0,%1,%2,%3},[%4];"
                 : "=r"(r0), "=r"(r1), "=r"(r2), "=r"(r3) : "r"(a));
}
__device__ __forceinline__ void mma16816(float* c, const uint32_t* a, uint32_t b0, uint32_t b1) {
    asm volatile("mma.sync.aligned.m16n8k16.row.col.f32.bf16.bf16.f32 "
                 "{%0,%1,%2,%3},{%4,%5,%6,%7},{%8,%9},{%0,%1,%2,%3};"
                 : "+f"(c[0]), "+f"(c[1]), "+f"(c[2]), "+f"(c[3])
                 : "r"(a[0]), "r"(a[1]), "r"(a[2]), "r"(a[3]), "r"(b0), "r"(b1));
}
__device__ __forceinline__ uint32_t pack_bf2(float a, float b) {
    __nv_bfloat162 h; h.x = __float2bfloat16(a); h.y = __float2bfloat16(b);
    return *(uint32_t*)&h;
}

// ---------------- detect int64 vs int32 edge indices ------------------------
__global__ void detect_kernel(const void* edge) {
    if (threadIdx.x == 0 && blockIdx.x == 0) {
        const unsigned long long* p = (const unsigned long long*)edge;
        int ok = 1;
        #pragma unroll
        for (int i = 0; i < 16; i++)
            if (p[i] >= (unsigned long long)NND) ok = 0;
        g_is64 = ok;
    }
}

__global__ void zero_deg_kernel() {
    int i = blockIdx.x * blockDim.x + threadIdx.x;
    if (i < NND) { g_degin[i] = 0; g_degout[i] = 0; }
}

__global__ void deg_kernel(const void* edge) {
    int is64 = g_is64;
    int stride = gridDim.x * blockDim.x;
    for (int e = blockIdx.x * blockDim.x + threadIdx.x; e < NED; e += stride) {
        int s = load_idx(edge, is64, e);
        int d = load_idx(edge, is64, (long long)NED + e);
        atomicAdd(&g_degout[s], 1);
        atomicAdd(&g_degin[d], 1);
    }
}

__global__ void norm_kernel() {
    int i = blockIdx.x * blockDim.x + threadIdx.x;
    if (i < NND) {
        g_csrc[i] = rsqrtf((float)max(g_degout[i], 1));
        g_cdst[i] = rsqrtf((float)max(g_degin[i], 1));
    }
}

// ---------------- single-block exclusive scan of degin -> off, cur ----------
#define NPT 49   // 1024*49 = 50176 >= 50000
__global__ __launch_bounds__(1024)
void scan_kernel() {
    __shared__ int sd[1024];
    int tid = threadIdx.x;
    int sum = 0;
    #pragma unroll
    for (int j = 0; j < NPT; j++) {
        int idx = tid * NPT + j;
        sum += (idx < NND) ? g_degin[idx] : 0;
    }
    sd[tid] = sum; __syncthreads();
    #pragma unroll
    for (int d = 1; d < 1024; d <<= 1) {
        int t = (tid >= d) ? sd[tid - d] : 0;
        __syncthreads();
        sd[tid] += t;
        __syncthreads();
    }
    int run = sd[tid] - sum;   // exclusive
    #pragma unroll
    for (int j = 0; j < NPT; j++) {
        int idx = tid * NPT + j;
        if (idx < NND) {
            g_off[idx] = run;
            g_cur[idx] = run;
            run += g_degin[idx];
        }
    }
    if (tid == 0) g_off[NND] = NED;
}

__global__ void fill_kernel(const void* edge) {
    int is64 = g_is64;
    int stride = gridDim.x * blockDim.x;
    for (int e = blockIdx.x * blockDim.x + threadIdx.x; e < NED; e += stride) {
        int s = load_idx(edge, is64, e);
        int d = load_idx(edge, is64, (long long)NED + e);
        int pos = atomicAdd(&g_cur[d], 1);
        g_srcl[pos] = s;
    }
}

// ---------------- bf16-split conversion of W1 -------------------------------
__global__ void convB_kernel(const float* __restrict__ W1) {
    long long total  = (long long)KP * (F1 / 2);
    long long stride = (long long)gridDim.x * blockDim.x;
    for (long long i = (long long)blockIdx.x * blockDim.x + threadIdx.x; i < total; i += stride) {
        int k  = (int)(i / (F1 / 2));
        int c2 = (int)(i % (F1 / 2)) * 2;
        float x0 = 0.f, x1 = 0.f;
        if (k < F0) { x0 = W1[(size_t)k * F1 + c2]; x1 = W1[(size_t)k * F1 + c2 + 1]; }
        __nv_bfloat16 h0 = __float2bfloat16(x0);
        __nv_bfloat16 h1 = __float2bfloat16(x1);
        __nv_bfloat16 l0 = __float2bfloat16(x0 - __bfloat162float(h0));
        __nv_bfloat16 l1 = __float2bfloat16(x1 - __bfloat162float(h1));
        __nv_bfloat162 hh; hh.x = h0; hh.y = h1;
        __nv_bfloat162 ll; ll.x = l0; ll.y = l1;
        *(__nv_bfloat162*)&g_Bh[(size_t)k * F1 + c2] = hh;
        *(__nv_bfloat162*)&g_Bl[(size_t)k * F1 + c2] = ll;
    }
}

// ---------------- GEMM1: fp32 A streamed, converted in-kernel ----------------
#define GBM 64
#define GBK 32
#define NT  (KP / GBK)         /* 45 */
#define ASTRB 80               /* A smem row stride bytes */
#define BSTRB 528
#define SA_SZ 5120             /* 64*80 */
#define SB_SZ 16896            /* 32*528 */
#define SMEM_TOTAL_G1 (4*SA_SZ + 4*SB_SZ)   /* 88064 */

extern __shared__ char g1_smem[];

__global__ __launch_bounds__(512, 1)
void gemm1_mma(const float* __restrict__ A,
               const __nv_bfloat16* __restrict__ Bh, const __nv_bfloat16* __restrict__ Bl,
               float* __restrict__ C, const float* __restrict__ csrc)
{
    const int tid = threadIdx.x;
    const int l   = tid & 31;
    const int wid = tid >> 5;
    const int mw  = (wid & 1) * 32;
    const int nw  = (wid >> 1) * 32;
    const int bm  = blockIdx.x * GBM;

    const uint32_t sbase = (uint32_t)__cvta_generic_to_shared(g1_smem);

    // A geometry: thread handles 4 consecutive fp32 of row a_row, cols a_c4*4..+3
    const int a_row = tid >> 3, a_c4 = tid & 7;
    const int a_grow = bm + a_row;
    const bool a_rv = (a_grow < NND);
    const float* a_src = A + (size_t)a_grow * F0 + a_c4 * 4;
    const uint32_t a_sts = (uint32_t)(a_row * ASTRB + a_c4 * 8);

    float acc[2][4][4];
    #pragma unroll
    for (int t = 0; t < 2; t++)
        #pragma unroll
        for (int j = 0; j < 4; j++)
            #pragma unroll
            for (int q = 0; q < 4; q++) acc[t][j][q] = 0.f;

    auto ldgA = [&](int kt, float* r) {
        int c0 = kt * GBK + a_c4 * 4;
        #pragma unroll
        for (int j = 0; j < 4; j++)
            r[j] = (a_rv && (c0 + j) < F0) ? __ldg(a_src + kt * GBK + j) : 0.f;
    };
    auto prefetchB = [&](int kt, int buf) {
        #pragma unroll
        for (int i = 0; i < 4; i++) {
            int cid = tid + 512 * i;
            int row = cid >> 6, sub = cid & 63, h = sub >> 5, c = sub & 31;
            const __nv_bfloat16* src = (h ? Bl : Bh) + (size_t)(kt * GBK + row) * F1 + c * 8;
            uint32_t dst = sbase + (uint32_t)(4 * SA_SZ + (buf * 2 + h) * SB_SZ + row * BSTRB + c * 16);
            cpa16(dst, src);
        }
    };

    float rcur[4], rnxt[4];
    ldgA(0, rcur);
    prefetchB(0, 0);
    CP_COMMIT();

    const int      lrow  = ((l >> 3) & 1) * 8 + (l & 7);
    const uint32_t acolb = (uint32_t)((l >> 4) * 16);
    const uint32_t bcolb = (uint32_t)((nw + ((l >> 4) ? 8 : 0)) * 2);

    for (int kt = 0; kt < NT; kt++) {
        const int buf = kt & 1;
        // convert current A tile regs -> smem bf16 hi/lo
        {
            uint32_t h01 = pack_bf2(rcur[0], rcur[1]);
            uint32_t h23 = pack_bf2(rcur[2], rcur[3]);
            float f0 = __bfloat162float(__float2bfloat16(rcur[0]));
            float f1 = __bfloat162float(__float2bfloat16(rcur[1]));
            float f2 = __bfloat162float(__float2bfloat16(rcur[2]));
            float f3 = __bfloat162float(__float2bfloat16(rcur[3]));
            uint32_t l01 = pack_bf2(rcur[0] - f0, rcur[1] - f1);
            uint32_t l23 = pack_bf2(rcur[2] - f2, rcur[3] - f3);
            char* base = g1_smem + buf * 2 * SA_SZ + a_sts;
            *(uint2*)base            = make_uint2(h01, h23);
            *(uint2*)(base + SA_SZ)  = make_uint2(l01, l23);
        }
        if (kt + 1 < NT) {
            prefetchB(kt + 1, buf ^ 1);
            ldgA(kt + 1, rnxt);
        }
        CP_COMMIT();
        CP_WAIT1();
        __syncthreads();

        const uint32_t sa0 = sbase + (uint32_t)(buf * 2 * SA_SZ);
        const uint32_t sa1 = sa0 + SA_SZ;
        const uint32_t sb0 = sbase + (uint32_t)(4 * SA_SZ + buf * 2 * SB_SZ);
        const uint32_t sb1 = sb0 + SB_SZ;

        #pragma unroll
        for (int ks = 0; ks < 2; ks++) {
            uint32_t ah[2][4], al_[2][4], bh[2][4], bl_[2][4];
            #pragma unroll
            for (int t = 0; t < 2; t++) {
                uint32_t off = (uint32_t)((mw + t * 16 + lrow) * ASTRB) + acolb + ks * 32;
                ldsm4(ah[t][0],  ah[t][1],  ah[t][2],  ah[t][3],  sa0 + off);
                ldsm4(al_[t][0], al_[t][1], al_[t][2], al_[t][3], sa1 + off);
            }
            const int brow = ks * 16 + lrow;
            #pragma unroll
            for (int g = 0; g < 2; g++) {
                uint32_t off = (uint32_t)(brow * BSTRB) + bcolb + (uint32_t)(g * 32);
                ldsm4t(bh[g][0],  bh[g][1],  bh[g][2],  bh[g][3],  sb0 + off);
                ldsm4t(bl_[g][0], bl_[g][1], bl_[g][2], bl_[g][3], sb1 + off);
            }
            #pragma unroll
            for (int t = 0; t < 2; t++)
                #pragma unroll
                for (int j = 0; j < 4; j++) {
                    uint32_t b0h = bh[j >> 1][(j & 1) * 2], b1h = bh[j >> 1][(j & 1) * 2 + 1];
                    uint32_t b0l = bl_[j >> 1][(j & 1) * 2], b1l = bl_[j >> 1][(j & 1) * 2 + 1];
                    mma16816(acc[t][j], ah[t],  b0h, b1h);
                    mma16816(acc[t][j], ah[t],  b0l, b1l);
                    mma16816(acc[t][j], al_[t], b0h, b1h);
                }
        }
        __syncthreads();
        #pragma unroll
        for (int j = 0; j < 4; j++) rcur[j] = rnxt[j];
    }

    #pragma unroll
    for (int t = 0; t < 2; t++) {
        int r0 = bm + mw + t * 16 + (l >> 2);
        #pragma unroll
        for (int half = 0; half < 2; half++) {
            int row = r0 + half * 8;
            if (row < NND) {
                float s = csrc[row];
                #pragma unroll
                for (int j = 0; j < 4; j++) {
                    int col = nw + j * 8 + (l & 3) * 2;
                    float2 v;
                    v.x = acc[t][j][half * 2]     * s;
                    v.y = acc[t][j][half * 2 + 1] * s;
                    *(float2*)&C[(size_t)row * F1 + col] = v;
                }
            }
        }
    }
}

// ---------------- CSR aggregation, F=256, fused relu(agg*cdst+b) ------------
__global__ __launch_bounds__(256)
void agg256_kernel(const float* __restrict__ h, float* __restrict__ xo,
                   const float* __restrict__ bias, const float* __restrict__ cdst) {
    int warp = (blockIdx.x * blockDim.x + threadIdx.x) >> 5;
    int lane = threadIdx.x & 31;
    if (warp >= NND) return;
    int i0 = g_off[warp], i1 = g_off[warp + 1];
    float4 a0 = make_float4(0.f, 0.f, 0.f, 0.f);
    float4 a1 = make_float4(0.f, 0.f, 0.f, 0.f);
    int i = i0;
    for (; i + 2 <= i1; i += 2) {
        int s0 = g_srcl[i], s1 = g_srcl[i + 1];
        const float4* r0 = (const float4*)(h + (size_t)s0 * 256) + lane * 2;
        const float4* r1 = (const float4*)(h + (size_t)s1 * 256) + lane * 2;
        float4 v00 = r0[0], v01 = r0[1], v10 = r1[0], v11 = r1[1];
        a0.x += v00.x; a0.y += v00.y; a0.z += v00.z; a0.w += v00.w;
        a1.x += v01.x; a1.y += v01.y; a1.z += v01.z; a1.w += v01.w;
        a0.x += v10.x; a0.y += v10.y; a0.z += v10.z; a0.w += v10.w;
        a1.x += v11.x; a1.y += v11.y; a1.z += v11.z; a1.w += v11.w;
    }
    if (i < i1) {
        int s0 = g_srcl[i];
        const float4* r0 = (const float4*)(h + (size_t)s0 * 256) + lane * 2;
        float4 v00 = r0[0], v01 = r0[1];
        a0.x += v00.x; a0.y += v00.y; a0.z += v00.z; a0.w += v00.w;
        a1.x += v01.x; a1.y += v01.y; a1.z += v01.z; a1.w += v01.w;
    }
    float c = cdst[warp];
    const float4* bp = (const float4*)bias + lane * 2;
    float4 b0 = bp[0], b1 = bp[1];
    float4 o0, o1;
    o0.x = fmaxf(fmaf(a0.x, c, b0.x), 0.f); o0.y = fmaxf(fmaf(a0.y, c, b0.y), 0.f);
    o0.z = fmaxf(fmaf(a0.z, c, b0.z), 0.f); o0.w = fmaxf(fmaf(a0.w, c, b0.w), 0.f);
    o1.x = fmaxf(fmaf(a1.x, c, b1.x), 0.f); o1.y = fmaxf(fmaf(a1.y, c, b1.y), 0.f);
    o1.z = fmaxf(fmaf(a1.z, c, b1.z), 0.f); o1.w = fmaxf(fmaf(a1.w, c, b1.w), 0.f);
    float4* op = (float4*)(xo + (size_t)warp * 256) + lane * 2;
    op[0] = o0; op[1] = o1;
}

// ---------------- CSR aggregation, F=32, fused relu -------------------------
__global__ __launch_bounds__(256)
void agg32_kernel(const float* __restrict__ h, float* __restrict__ xo,
                  const float* __restrict__ bias, const float* __restrict__ cdst) {
    int warp = (blockIdx.x * blockDim.x + threadIdx.x) >> 5;
    int lane = threadIdx.x & 31;
    if (warp >= NND) return;
    int i0 = g_off[warp], i1 = g_off[warp + 1];
    float a0 = 0.f, a1 = 0.f, a2 = 0.f, a3 = 0.f;
    int i = i0;
    for (; i + 4 <= i1; i += 4) {
        int s0 = g_srcl[i], s1 = g_srcl[i + 1], s2 = g_srcl[i + 2], s3 = g_srcl[i + 3];
        a0 += h[(size_t)s0 * 32 + lane];
        a1 += h[(size_t)s1 * 32 + lane];
        a2 += h[(size_t)s2 * 32 + lane];
        a3 += h[(size_t)s3 * 32 + lane];
    }
    for (; i < i1; i++) a0 += h[(size_t)g_srcl[i] * 32 + lane];
    float a = (a0 + a1) + (a2 + a3);
    xo[(size_t)warp * 32 + lane] = fmaxf(fmaf(a, cdst[warp], bias[lane]), 0.f);
}

// ---------------- CSR aggregation F=7 + log_softmax -------------------------
__global__ __launch_bounds__(256)
void agg7_final_kernel(const float* __restrict__ h, const float* __restrict__ b3,
                       const float* __restrict__ cdst, float* __restrict__ out) {
    int warp = (blockIdx.x * blockDim.x + threadIdx.x) >> 5;
    int lane = threadIdx.x & 31;
    int sub  = lane & 7;             // 0..7, col (7 = inactive)
    int node = warp * 4 + (lane >> 3);
    if (node >= NND) return;
    int i0 = g_off[node], i1 = g_off[node + 1];
    float a = 0.f;
    if (sub < 7)
        for (int i = i0; i < i1; i++) a += h[(size_t)g_srcl[i] * 8 + sub];
    float v = (sub < 7) ? fmaf(a, cdst[node], b3[sub]) : -1e30f;
    float mx = v;
    #pragma unroll
    for (int d = 1; d < 8; d <<= 1)
        mx = fmaxf(mx, __shfl_xor_sync(0xFFFFFFFFu, mx, d));
    float e = (sub < 7) ? expf(v - mx) : 0.f;
    float se = e;
    #pragma unroll
    for (int d = 1; d < 8; d <<= 1)
        se += __shfl_xor_sync(0xFFFFFFFFu, se, d);
    float lse = logf(se);
    if (sub < 7) out[(size_t)node * 7 + sub] = v - mx - lse;
}

// ---------------- GEMM2: [50000,256] @ [256,32], * c_src --------------------
__global__ __launch_bounds__(1024)
void gemm2_kernel(const float* __restrict__ x1, const float* __restrict__ W2,
                  float* __restrict__ h2, const float* __restrict__ csrc) {
    __shared__ float Ws[256 * 32];
    int tid = threadIdx.x;
    for (int i = tid; i < 256 * 32; i += 1024) Ws[i] = W2[i];
    __syncthreads();
    int m = blockIdx.x * 32 + (tid >> 5);
    int c = tid & 31;
    if (m >= NND) return;
    const float4* xr = (const float4*)(x1 + (size_t)m * 256);
    float acc = 0.f;
    #pragma unroll
    for (int k4 = 0; k4 < 64; k4++) {
        float4 x = xr[k4];
        int k = k4 * 4;
        acc = fmaf(x.x, Ws[(k + 0) * 32 + c], acc);
        acc = fmaf(x.y, Ws[(k + 1) * 32 + c], acc);
        acc = fmaf(x.z, Ws[(k + 2) * 32 + c], acc);
        acc = fmaf(x.w, Ws[(k + 3) * 32 + c], acc);
    }
    h2[(size_t)m * 32 + c] = acc * csrc[m];
}

// ---------------- GEMM3: [50000,32] @ [32,7], * c_src (stride-8 out) --------
__global__ void gemm3_kernel(const float* __restrict__ x2, const float* __restrict__ W3,
                             float* __restrict__ h3, const float* __restrict__ csrc) {
    __shared__ float Ws[32 * 7];
    int tid = threadIdx.x;
    if (tid < 224) Ws[tid] = W3[tid];
    __syncthreads();
    int m = blockIdx.x * blockDim.x + tid;
    if (m >= NND) return;
    const float4* xr = (const float4*)(x2 + (size_t)m * 32);
    float x[32];
    #pragma unroll
    for (int i = 0; i < 8; i++) {
        float4 v = xr[i];
        x[4 * i] = v.x; x[4 * i + 1] = v.y; x[4 * i + 2] = v.z; x[4 * i + 3] = v.w;
    }
    float s = csrc[m];
    #pragma unroll
    for (int j = 0; j < 7; j++) {
        float a = 0.f;
        #pragma unroll
        for (int k = 0; k < 32; k++) a = fmaf(x[k], Ws[k * 7 + j], a);
        h3[(size_t)m * 8 + j] = a * s;
    }
}

// ---------------- host ------------------------------------------------------
extern "C" void kernel_launch(void* const* d_in, const int* in_sizes, int n_in,
                              void* d_out, int out_size) {
    const float* feat = (const float*)d_in[0];
    const void*  edge = d_in[1];
    const float* W1   = (const float*)d_in[2];
    const float* b1   = (const float*)d_in[3];
    const float* W2   = (const float*)d_in[4];
    const float* b2   = (const float*)d_in[5];
    const float* W3   = (const float*)d_in[6];
    const float* b3   = (const float*)d_in[7];
    float* out = (float*)d_out;

    float *p_csrc, *p_cdst, *p_h1, *p_x1, *p_h2, *p_x2, *p_h3;
    __nv_bfloat16 *p_Bh, *p_Bl;
    cudaGetSymbolAddress((void**)&p_csrc, g_csrc);
    cudaGetSymbolAddress((void**)&p_cdst, g_cdst);
    cudaGetSymbolAddress((void**)&p_h1,   g_h1);
    cudaGetSymbolAddress((void**)&p_x1,   g_x1);
    cudaGetSymbolAddress((void**)&p_h2,   g_h2);
    cudaGetSymbolAddress((void**)&p_x2,   g_x2);
    cudaGetSymbolAddress((void**)&p_h3,   g_h3);
    cudaGetSymbolAddress((void**)&p_Bh,   g_Bh);
    cudaGetSymbolAddress((void**)&p_Bl,   g_Bl);

    static int smem_set = 0;
    if (!smem_set) {
        cudaFuncSetAttribute(gemm1_mma, cudaFuncAttributeMaxDynamicSharedMemorySize, SMEM_TOTAL_G1);
        smem_set = 1;
    }

    detect_kernel<<<1, 1>>>(edge);
    zero_deg_kernel<<<(NND + 255) / 256, 256>>>();
    deg_kernel<<<1024, 256>>>(edge);
    norm_kernel<<<(NND + 255) / 256, 256>>>();
    scan_kernel<<<1, 1024>>>();
    fill_kernel<<<1024, 256>>>(edge);
    convB_kernel<<<256, 256>>>(W1);

    // Layer 1
    gemm1_mma<<<MP / GBM, 512, SMEM_TOTAL_G1>>>(feat, p_Bh, p_Bl, p_h1, p_csrc);
    agg256_kernel<<<(NND * 32 + 255) / 256, 256>>>(p_h1, p_x1, b1, p_cdst);

    // Layer 2
    gemm2_kernel<<<(NND + 31) / 32, 1024>>>(p_x1, W2, p_h2, p_csrc);
    agg32_kernel<<<(NND * 32 + 255) / 256, 256>>>(p_h2, p_x2, b2, p_cdst);

    // Layer 3
    gemm3_kernel<<<(NND + 255) / 256, 256>>>(p_x2, W3, p_h3, p_csrc);
    agg7_final_kernel<<<((NND + 3) / 4 * 32 + 255) / 256, 256>>>(p_h3, b3, p_cdst, out);
}

// round 6
// speedup vs baseline: 2.3001x; 1.1559x over previous
#include <cuda_runtime.h>
#include <cuda_bf16.h>
#include <cstdint>
#include <cstddef>

#define NND 50000
#define NED 800000
#define F0 1433
#define KP 1440            // 45 * 32
#define NKT 45
#define F1 256
#define F2 32

// ---------------- device scratch -------------------------------------------
__device__ float g_csrc[NND];
__device__ float g_cdst[NND];
__device__ float g_h1[(size_t)NND * F1];
__device__ float g_x1[(size_t)NND * F1];
__device__ float g_h2[(size_t)NND * F2];
__device__ float g_x2[(size_t)NND * F2];
__device__ float g_h3[(size_t)NND * 8];
__device__ int   g_is64;
__device__ int   g_degin[NND];
__device__ int   g_degout[NND];
__device__ int   g_off[NND + 1];
__device__ int   g_cur[NND];
__device__ int   g_srcl[NED];
// W1^T as tf32: [n=256][k=KP]
__device__ uint32_t g_Btt[(size_t)F1 * KP];

// ---------------- helpers ---------------------------------------------------
__device__ __forceinline__ int load_idx(const void* edge, int is64, long long lin) {
    if (is64) return (int)((const long long*)edge)[lin];
    return ((const int*)edge)[lin];
}
__device__ __forceinline__ void cpa16(uint32_t dst, const void* src) {
    asm volatile("cp.async.cg.shared.global [%0],[%1],16;" :: "r"(dst), "l"(src));
}
#define CP_COMMIT() asm volatile("cp.async.commit_group;")
#define CP_WAIT1()  asm volatile("cp.async.wait_group 1;" ::: "memory")

__device__ __forceinline__ void ldsm4(uint32_t& r0, uint32_t& r1, uint32_t& r2, uint32_t& r3, uint32_t a) {
    asm volatile("ldmatrix.sync.aligned.m8n8.x4.shared.b16 {%0,%1,%2,%3},[%4];"
                 : "=r"(r0), "=r"(r1), "=r"(r2), "=r"(r3) : "r"(a));
}
__device__ __forceinline__ void mma_tf32(float* c, const uint32_t* a, uint32_t b0, uint32_t b1) {
    asm volatile("mma.sync.aligned.m16n8k8.row.col.f32.tf32.tf32.f32 "
                 "{%0,%1,%2,%3},{%4,%5,%6,%7},{%8,%9},{%0,%1,%2,%3};"
                 : "+f"(c[0]), "+f"(c[1]), "+f"(c[2]), "+f"(c[3])
                 : "r"(a[0]), "r"(a[1]), "r"(a[2]), "r"(a[3]), "r"(b0), "r"(b1));
}
__device__ __forceinline__ uint32_t f2tf32(float x) {
    uint32_t r;
    asm("cvt.rna.tf32.f32 %0, %1;" : "=r"(r) : "f"(x));
    return r;
}
__device__ __forceinline__ uint32_t smem_u32(const void* p) {
    uint32_t a;
    asm("{ .reg .u64 t; cvta.to.shared.u64 t, %1; cvt.u32.u64 %0, t; }" : "=r"(a) : "l"(p));
    return a;
}

// ---------------- detect + zero degrees -------------------------------------
__global__ void init_kernel(const void* edge) {
    int i = blockIdx.x * blockDim.x + threadIdx.x;
    if (i == 0) {
        const unsigned long long* p = (const unsigned long long*)edge;
        int ok = 1;
        #pragma unroll
        for (int j = 0; j < 16; j++)
            if (p[j] >= (unsigned long long)NND) ok = 0;
        g_is64 = ok;
    }
    if (i < NND) { g_degin[i] = 0; g_degout[i] = 0; }
}

__global__ void deg_kernel(const void* edge) {
    int is64 = g_is64;
    int stride = gridDim.x * blockDim.x;
    for (int e = blockIdx.x * blockDim.x + threadIdx.x; e < NED; e += stride) {
        int s = load_idx(edge, is64, e);
        int d = load_idx(edge, is64, (long long)NED + e);
        atomicAdd(&g_degout[s], 1);
        atomicAdd(&g_degin[d], 1);
    }
}

__global__ void norm_kernel() {
    int i = blockIdx.x * blockDim.x + threadIdx.x;
    if (i < NND) {
        g_csrc[i] = rsqrtf((float)max(g_degout[i], 1));
        g_cdst[i] = rsqrtf((float)max(g_degin[i], 1));
    }
}

// ---------------- single-block exclusive scan of degin -> off, cur ----------
#define NPT 49
__global__ __launch_bounds__(1024)
void scan_kernel() {
    __shared__ int sd[1024];
    int tid = threadIdx.x;
    int sum = 0;
    #pragma unroll
    for (int j = 0; j < NPT; j++) {
        int idx = tid * NPT + j;
        sum += (idx < NND) ? g_degin[idx] : 0;
    }
    sd[tid] = sum; __syncthreads();
    #pragma unroll
    for (int d = 1; d < 1024; d <<= 1) {
        int t = (tid >= d) ? sd[tid - d] : 0;
        __syncthreads();
        sd[tid] += t;
        __syncthreads();
    }
    int run = sd[tid] - sum;
    #pragma unroll
    for (int j = 0; j < NPT; j++) {
        int idx = tid * NPT + j;
        if (idx < NND) {
            g_off[idx] = run;
            g_cur[idx] = run;
            run += g_degin[idx];
        }
    }
    if (tid == 0) g_off[NND] = NED;
}

__global__ void fill_kernel(const void* edge) {
    int is64 = g_is64;
    int stride = gridDim.x * blockDim.x;
    for (int e = blockIdx.x * blockDim.x + threadIdx.x; e < NED; e += stride) {
        int s = load_idx(edge, is64, e);
        int d = load_idx(edge, is64, (long long)NED + e);
        int pos = atomicAdd(&g_cur[d], 1);
        g_srcl[pos] = s;
    }
}

// ---------------- W1^T tf32 conversion --------------------------------------
__global__ void convBt_kernel(const float* __restrict__ W1) {
    int i = blockIdx.x * blockDim.x + threadIdx.x;
    if (i >= F1 * KP) return;
    int n = i / KP, k = i % KP;
    float x = (k < F0) ? W1[(size_t)k * F1 + n] : 0.f;
    g_Btt[i] = f2tf32(x);
}

// ---------------- GEMM1: tf32 mma.sync, M=128 N=256, 3-stage ----------------
// smem per stage: A 128 rows x 144B, B 256 rows x 144B
#define ASTR 144
#define SA_SZ (128 * ASTR)        /* 18432 */
#define SB_SZ (256 * ASTR)        /* 36864 */
#define STAGE (SA_SZ + SB_SZ)     /* 55296 */
#define SMEM_G1 (3 * STAGE)       /* 165888 */

extern __shared__ char g1s[];

__global__ __launch_bounds__(512, 1)
void gemm1_tf32(const float* __restrict__ A, const uint32_t* __restrict__ Btt,
                float* __restrict__ C, const float* __restrict__ csrc)
{
    const int tid = threadIdx.x;
    const int l   = tid & 31;
    const int wid = tid >> 5;
    const int mw  = (wid & 1) * 64;
    const int nw  = (wid >> 1) * 32;
    const int bm  = blockIdx.x * 128;
    const uint32_t sb = smem_u32(g1s);

    // A ldg geometry: row = tid>>2 (128 rows), cg = tid&3 -> cols cg*8..+7
    const int a_row = tid >> 2, a_cg = tid & 3;
    const int a_grow = bm + a_row;
    const bool a_rv = (a_grow < NND);
    const float* a_base = A + (size_t)a_grow * F0 + a_cg * 8;

    float acc[4][4][4];
    #pragma unroll
    for (int t = 0; t < 4; t++)
        #pragma unroll
        for (int j = 0; j < 4; j++)
            #pragma unroll
            for (int q = 0; q < 4; q++) acc[t][j][q] = 0.f;

    float rA[8];
    auto ldgA = [&](int kt) {
        int c0 = kt * 32 + a_cg * 8;
        #pragma unroll
        for (int j = 0; j < 8; j++)
            rA[j] = (a_rv && (c0 + j) < F0) ? a_base[kt * 32 + j] : 0.f;
    };
    auto stsA = [&](int buf) {
        uint32_t w[8];
        #pragma unroll
        for (int j = 0; j < 8; j++) w[j] = f2tf32(rA[j]);
        char* dst = g1s + buf * STAGE + a_row * ASTR + a_cg * 32;
        *(uint4*)dst        = make_uint4(w[0], w[1], w[2], w[3]);
        *(uint4*)(dst + 16) = make_uint4(w[4], w[5], w[6], w[7]);
    };
    auto cpB = [&](int kt, int buf) {
        #pragma unroll
        for (int i = 0; i < 4; i++) {
            int ch = tid * 4 + i;                 // 0..2047
            int n = ch >> 3, k16 = ch & 7;
            uint32_t dst = sb + (uint32_t)(buf * STAGE + SA_SZ + n * ASTR + k16 * 16);
            cpa16(dst, Btt + (size_t)n * KP + kt * 32 + k16 * 4);
        }
    };

    // prologue
    ldgA(0); cpB(0, 0); CP_COMMIT();
    stsA(0);
    ldgA(1); cpB(1, 1); CP_COMMIT();

    const int      lrow = ((l >> 3) & 1) * 8 + (l & 7);
    const uint32_t acol = (uint32_t)((l >> 4) * 16);
    const uint32_t brow = (uint32_t)(nw + ((l >> 4) & 1) * 8 + (l & 7));
    const uint32_t bcol = (uint32_t)(((l >> 3) & 1) * 16);

    for (int kt = 0; kt < NKT; kt++) {
        CP_WAIT1();
        __syncthreads();
        if (kt + 1 < NKT) stsA((kt + 1) % 3);
        if (kt + 2 < NKT) { cpB(kt + 2, (kt + 2) % 3); ldgA(kt + 2); }
        CP_COMMIT();

        const int buf = kt % 3;
        const uint32_t sa  = sb + (uint32_t)(buf * STAGE);
        const uint32_t sbb = sa + SA_SZ;

        #pragma unroll
        for (int ks = 0; ks < 4; ks++) {
            uint32_t bb[8];
            uint32_t ba = sbb + brow * ASTR + (uint32_t)(ks * 32) + bcol;
            ldsm4(bb[0], bb[1], bb[2], bb[3], ba);
            ldsm4(bb[4], bb[5], bb[6], bb[7], ba + 16 * ASTR);
            #pragma unroll
            for (int t = 0; t < 4; t++) {
                uint32_t aa[4];
                uint32_t aadr = sa + (uint32_t)((mw + t * 16 + lrow) * ASTR + ks * 32) + acol;
                ldsm4(aa[0], aa[1], aa[2], aa[3], aadr);
                mma_tf32(acc[t][0], aa, bb[0], bb[1]);
                mma_tf32(acc[t][1], aa, bb[2], bb[3]);
                mma_tf32(acc[t][2], aa, bb[4], bb[5]);
                mma_tf32(acc[t][3], aa, bb[6], bb[7]);
            }
        }
        __syncthreads();
    }

    // epilogue: * csrc, store fp32
    #pragma unroll
    for (int t = 0; t < 4; t++) {
        int r0 = bm + mw + t * 16 + (l >> 2);
        #pragma unroll
        for (int half = 0; half < 2; half++) {
            int row = r0 + half * 8;
            if (row < NND) {
                float s = csrc[row];
                #pragma unroll
                for (int j = 0; j < 4; j++) {
                    int col = nw + j * 8 + (l & 3) * 2;
                    float2 v;
                    v.x = acc[t][j][half * 2]     * s;
                    v.y = acc[t][j][half * 2 + 1] * s;
                    *(float2*)&C[(size_t)row * F1 + col] = v;
                }
            }
        }
    }
}

// ---------------- CSR aggregation, F=256, fused relu(agg*cdst+b) ------------
__global__ __launch_bounds__(256)
void agg256_kernel(const float* __restrict__ h, float* __restrict__ xo,
                   const float* __restrict__ bias, const float* __restrict__ cdst) {
    int warp = (blockIdx.x * blockDim.x + threadIdx.x) >> 5;
    int lane = threadIdx.x & 31;
    if (warp >= NND) return;
    int i0 = g_off[warp], i1 = g_off[warp + 1];
    float4 a0 = make_float4(0.f, 0.f, 0.f, 0.f);
    float4 a1 = make_float4(0.f, 0.f, 0.f, 0.f);
    int i = i0;
    for (; i + 2 <= i1; i += 2) {
        int s0 = g_srcl[i], s1 = g_srcl[i + 1];
        const float4* r0 = (const float4*)(h + (size_t)s0 * 256) + lane * 2;
        const float4* r1 = (const float4*)(h + (size_t)s1 * 256) + lane * 2;
        float4 v00 = r0[0], v01 = r0[1], v10 = r1[0], v11 = r1[1];
        a0.x += v00.x; a0.y += v00.y; a0.z += v00.z; a0.w += v00.w;
        a1.x += v01.x; a1.y += v01.y; a1.z += v01.z; a1.w += v01.w;
        a0.x += v10.x; a0.y += v10.y; a0.z += v10.z; a0.w += v10.w;
        a1.x += v11.x; a1.y += v11.y; a1.z += v11.z; a1.w += v11.w;
    }
    if (i < i1) {
        int s0 = g_srcl[i];
        const float4* r0 = (const float4*)(h + (size_t)s0 * 256) + lane * 2;
        float4 v00 = r0[0], v01 = r0[1];
        a0.x += v00.x; a0.y += v00.y; a0.z += v00.z; a0.w += v00.w;
        a1.x += v01.x; a1.y += v01.y; a1.z += v01.z; a1.w += v01.w;
    }
    float c = cdst[warp];
    const float4* bp = (const float4*)bias + lane * 2;
    float4 b0 = bp[0], b1 = bp[1];
    float4 o0, o1;
    o0.x = fmaxf(fmaf(a0.x, c, b0.x), 0.f); o0.y = fmaxf(fmaf(a0.y, c, b0.y), 0.f);
    o0.z = fmaxf(fmaf(a0.z, c, b0.z), 0.f); o0.w = fmaxf(fmaf(a0.w, c, b0.w), 0.f);
    o1.x = fmaxf(fmaf(a1.x, c, b1.x), 0.f); o1.y = fmaxf(fmaf(a1.y, c, b1.y), 0.f);
    o1.z = fmaxf(fmaf(a1.z, c, b1.z), 0.f); o1.w = fmaxf(fmaf(a1.w, c, b1.w), 0.f);
    float4* op = (float4*)(xo + (size_t)warp * 256) + lane * 2;
    op[0] = o0; op[1] = o1;
}

// ---------------- CSR aggregation, F=32, fused relu -------------------------
__global__ __launch_bounds__(256)
void agg32_kernel(const float* __restrict__ h, float* __restrict__ xo,
                  const float* __restrict__ bias, const float* __restrict__ cdst) {
    int warp = (blockIdx.x * blockDim.x + threadIdx.x) >> 5;
    int lane = threadIdx.x & 31;
    if (warp >= NND) return;
    int i0 = g_off[warp], i1 = g_off[warp + 1];
    float a0 = 0.f, a1 = 0.f, a2 = 0.f, a3 = 0.f;
    int i = i0;
    for (; i + 4 <= i1; i += 4) {
        int s0 = g_srcl[i], s1 = g_srcl[i + 1], s2 = g_srcl[i + 2], s3 = g_srcl[i + 3];
        a0 += h[(size_t)s0 * 32 + lane];
        a1 += h[(size_t)s1 * 32 + lane];
        a2 += h[(size_t)s2 * 32 + lane];
        a3 += h[(size_t)s3 * 32 + lane];
    }
    for (; i < i1; i++) a0 += h[(size_t)g_srcl[i] * 32 + lane];
    float a = (a0 + a1) + (a2 + a3);
    xo[(size_t)warp * 32 + lane] = fmaxf(fmaf(a, cdst[warp], bias[lane]), 0.f);
}

// ---------------- CSR aggregation F=7 + log_softmax -------------------------
__global__ __launch_bounds__(256)
void agg7_final_kernel(const float* __restrict__ h, const float* __restrict__ b3,
                       const float* __restrict__ cdst, float* __restrict__ out) {
    int warp = (blockIdx.x * blockDim.x + threadIdx.x) >> 5;
    int lane = threadIdx.x & 31;
    int sub  = lane & 7;
    int node = warp * 4 + (lane >> 3);
    if (node >= NND) return;
    int i0 = g_off[node], i1 = g_off[node + 1];
    float a = 0.f;
    if (sub < 7)
        for (int i = i0; i < i1; i++) a += h[(size_t)g_srcl[i] * 8 + sub];
    float v = (sub < 7) ? fmaf(a, cdst[node], b3[sub]) : -1e30f;
    float mx = v;
    #pragma unroll
    for (int d = 1; d < 8; d <<= 1)
        mx = fmaxf(mx, __shfl_xor_sync(0xFFFFFFFFu, mx, d));
    float e = (sub < 7) ? expf(v - mx) : 0.f;
    float se = e;
    #pragma unroll
    for (int d = 1; d < 8; d <<= 1)
        se += __shfl_xor_sync(0xFFFFFFFFu, se, d);
    float lse = logf(se);
    if (sub < 7) out[(size_t)node * 7 + sub] = v - mx - lse;
}

// ---------------- GEMM2: [50000,256] @ [256,32], * c_src --------------------
__global__ __launch_bounds__(1024)
void gemm2_kernel(const float* __restrict__ x1, const float* __restrict__ W2,
                  float* __restrict__ h2, const float* __restrict__ csrc) {
    __shared__ float Ws[256 * 32];
    int tid = threadIdx.x;
    for (int i = tid; i < 256 * 32; i += 1024) Ws[i] = W2[i];
    __syncthreads();
    int m = blockIdx.x * 32 + (tid >> 5);
    int c = tid & 31;
    if (m >= NND) return;
    const float4* xr = (const float4*)(x1 + (size_t)m * 256);
    float acc = 0.f;
    #pragma unroll
    for (int k4 = 0; k4 < 64; k4++) {
        float4 x = xr[k4];
        int k = k4 * 4;
        acc = fmaf(x.x, Ws[(k + 0) * 32 + c], acc);
        acc = fmaf(x.y, Ws[(k + 1) * 32 + c], acc);
        acc = fmaf(x.z, Ws[(k + 2) * 32 + c], acc);
        acc = fmaf(x.w, Ws[(k + 3) * 32 + c], acc);
    }
    h2[(size_t)m * 32 + c] = acc * csrc[m];
}

// ---------------- GEMM3: [50000,32] @ [32,7], * c_src (stride-8 out) --------
__global__ void gemm3_kernel(const float* __restrict__ x2, const float* __restrict__ W3,
                             float* __restrict__ h3, const float* __restrict__ csrc) {
    __shared__ float Ws[32 * 7];
    int tid = threadIdx.x;
    if (tid < 224) Ws[tid] = W3[tid];
    __syncthreads();
    int m = blockIdx.x * blockDim.x + tid;
    if (m >= NND) return;
    const float4* xr = (const float4*)(x2 + (size_t)m * 32);
    float x[32];
    #pragma unroll
    for (int i = 0; i < 8; i++) {
        float4 v = xr[i];
        x[4 * i] = v.x; x[4 * i + 1] = v.y; x[4 * i + 2] = v.z; x[4 * i + 3] = v.w;
    }
    float s = csrc[m];
    #pragma unroll
    for (int j = 0; j < 7; j++) {
        float a = 0.f;
        #pragma unroll
        for (int k = 0; k < 32; k++) a = fmaf(x[k], Ws[k * 7 + j], a);
        h3[(size_t)m * 8 + j] = a * s;
    }
}

// ---------------- host ------------------------------------------------------
extern "C" void kernel_launch(void* const* d_in, const int* in_sizes, int n_in,
                              void* d_out, int out_size) {
    const float* feat = (const float*)d_in[0];
    const void*  edge = d_in[1];
    const float* W1   = (const float*)d_in[2];
    const float* b1   = (const float*)d_in[3];
    const float* W2   = (const float*)d_in[4];
    const float* b2   = (const float*)d_in[5];
    const float* W3   = (const float*)d_in[6];
    const float* b3   = (const float*)d_in[7];
    float* out = (float*)d_out;

    float *p_csrc, *p_cdst, *p_h1, *p_x1, *p_h2, *p_x2, *p_h3;
    uint32_t* p_Btt;
    cudaGetSymbolAddress((void**)&p_csrc, g_csrc);
    cudaGetSymbolAddress((void**)&p_cdst, g_cdst);
    cudaGetSymbolAddress((void**)&p_h1,   g_h1);
    cudaGetSymbolAddress((void**)&p_x1,   g_x1);
    cudaGetSymbolAddress((void**)&p_h2,   g_h2);
    cudaGetSymbolAddress((void**)&p_x2,   g_x2);
    cudaGetSymbolAddress((void**)&p_h3,   g_h3);
    cudaGetSymbolAddress((void**)&p_Btt,  g_Btt);

    static int smem_set = 0;
    if (!smem_set) {
        cudaFuncSetAttribute(gemm1_tf32, cudaFuncAttributeMaxDynamicSharedMemorySize, SMEM_G1);
        smem_set = 1;
    }

    init_kernel<<<(NND + 255) / 256, 256>>>(edge);
    deg_kernel<<<1024, 256>>>(edge);
    norm_kernel<<<(NND + 255) / 256, 256>>>();
    scan_kernel<<<1, 1024>>>();
    fill_kernel<<<1024, 256>>>(edge);
    convBt_kernel<<<(F1 * KP + 255) / 256, 256>>>(W1);

    // Layer 1 (tf32 mma.sync)
    gemm1_tf32<<<(NND + 127) / 128, 512, SMEM_G1>>>(feat, p_Btt, p_h1, p_csrc);
    agg256_kernel<<<(NND * 32 + 255) / 256, 256>>>(p_h1, p_x1, b1, p_cdst);

    // Layer 2
    gemm2_kernel<<<(NND + 31) / 32, 1024>>>(p_x1, W2, p_h2, p_csrc);
    agg32_kernel<<<(NND * 32 + 255) / 256, 256>>>(p_h2, p_x2, b2, p_cdst);

    // Layer 3
    gemm3_kernel<<<(NND + 255) / 256, 256>>>(p_x2, W3, p_h3, p_csrc);
    agg7_final_kernel<<<((NND + 3) / 4 * 32 + 255) / 256, 256>>>(p_h3, b3, p_cdst, out);
}

// round 7
// speedup vs baseline: 3.7671x; 1.6378x over previous
#include <cuda_runtime.h>
#include <cuda_fp16.h>
#include <cstdint>
#include <cstddef>

#define NND 50000
#define NED 800000
#define F0 1433
#define KP 1440            // 45 * 32
#define NKT 45
#define F1 256
#define F2 32
#define NBS 196            // scan blocks: 196*256 = 50176

// ---------------- device scratch -------------------------------------------
__device__ float g_csrc[NND];
__device__ float g_cdst[NND];
__device__ __half g_h1[(size_t)NND * F1];
__device__ float g_x1[(size_t)NND * F1];
__device__ float g_h2[(size_t)NND * F2];
__device__ float g_x2[(size_t)NND * F2];
__device__ float g_h3[(size_t)NND * 8];
__device__ int   g_is64;
__device__ int   g_degin[NND];
__device__ int   g_degout[NND];
__device__ int   g_off[NND + 1];
__device__ int   g_cur[NND];
__device__ int   g_srcl[NED];
__device__ int   g_bsum[NBS];
__device__ int   g_bpre[NBS];
// W1^T as fp16: [n=256][k=KP]
__device__ __half g_Bt[(size_t)F1 * KP];

// ---------------- helpers ---------------------------------------------------
__device__ __forceinline__ int load_idx(const void* edge, int is64, long long lin) {
    if (is64) return (int)((const long long*)edge)[lin];
    return ((const int*)edge)[lin];
}
__device__ __forceinline__ void cpa16(uint32_t dst, const void* src) {
    asm volatile("cp.async.cg.shared.global [%0],[%1],16;" :: "r"(dst), "l"(src));
}
#define CP_COMMIT() asm volatile("cp.async.commit_group;")
#define CP_WAIT1()  asm volatile("cp.async.wait_group 1;" ::: "memory")

__device__ __forceinline__ void ldsm4(uint32_t& r0, uint32_t& r1, uint32_t& r2, uint32_t& r3, uint32_t a) {
    asm volatile("ldmatrix.sync.aligned.m8n8.x4.shared.b16 {%0,%1,%2,%3},[%4];"
                 : "=r"(r0), "=r"(r1), "=r"(r2), "=r"(r3) : "r"(a));
}
__device__ __forceinline__ void mma_f16(float* c, const uint32_t* a, uint32_t b0, uint32_t b1) {
    asm volatile("mma.sync.aligned.m16n8k16.row.col.f32.f16.f16.f32 "
                 "{%0,%1,%2,%3},{%4,%5,%6,%7},{%8,%9},{%0,%1,%2,%3};"
                 : "+f"(c[0]), "+f"(c[1]), "+f"(c[2]), "+f"(c[3])
                 : "r"(a[0]), "r"(a[1]), "r"(a[2]), "r"(a[3]), "r"(b0), "r"(b1));
}
__device__ __forceinline__ uint32_t smem_u32(const void* p) {
    uint32_t a;
    asm("{ .reg .u64 t; cvta.to.shared.u64 t, %1; cvt.u32.u64 %0, t; }" : "=r"(a) : "l"(p));
    return a;
}
__device__ __forceinline__ uint32_t pack_h2(float a, float b) {
    __half2 h = __floats2half2_rn(a, b);
    return *(uint32_t*)&h;
}

// ---------------- detect + zero degrees -------------------------------------
__global__ void init_kernel(const void* edge) {
    int i = blockIdx.x * blockDim.x + threadIdx.x;
    if (i == 0) {
        const unsigned long long* p = (const unsigned long long*)edge;
        int ok = 1;
        #pragma unroll
        for (int j = 0; j < 16; j++)
            if (p[j] >= (unsigned long long)NND) ok = 0;
        g_is64 = ok;
    }
    if (i < NND) { g_degin[i] = 0; g_degout[i] = 0; }
}

__global__ void deg_kernel(const void* edge) {
    int is64 = g_is64;
    int stride = gridDim.x * blockDim.x;
    for (int e = blockIdx.x * blockDim.x + threadIdx.x; e < NED; e += stride) {
        int s = load_idx(edge, is64, e);
        int d = load_idx(edge, is64, (long long)NED + e);
        atomicAdd(&g_degout[s], 1);
        atomicAdd(&g_degin[d], 1);
    }
}

// ---------------- 3-phase coalesced scan ------------------------------------
__global__ __launch_bounds__(256) void scanA_kernel() {
    __shared__ int sd[256];
    int t = threadIdx.x, b = blockIdx.x;
    int idx = b * 256 + t;
    int d = (idx < NND) ? g_degin[idx] : 0;
    sd[t] = d; __syncthreads();
    #pragma unroll
    for (int s = 1; s < 256; s <<= 1) {
        int v = (t >= s) ? sd[t - s] : 0;
        __syncthreads();
        sd[t] += v;
        __syncthreads();
    }
    if (idx < NND) g_off[idx] = sd[t] - d;     // block-exclusive
    if (t == 255) g_bsum[b] = sd[255];
}
__global__ __launch_bounds__(256) void scanB_kernel() {
    __shared__ int sd[256];
    int t = threadIdx.x;
    int d = (t < NBS) ? g_bsum[t] : 0;
    sd[t] = d; __syncthreads();
    #pragma unroll
    for (int s = 1; s < 256; s <<= 1) {
        int v = (t >= s) ? sd[t - s] : 0;
        __syncthreads();
        sd[t] += v;
        __syncthreads();
    }
    if (t < NBS) g_bpre[t] = sd[t] - d;
}
__global__ __launch_bounds__(256) void scanC_kernel() {
    int t = threadIdx.x, b = blockIdx.x;
    int idx = b * 256 + t;
    if (idx < NND) {
        int off = g_off[idx] + g_bpre[b];
        g_off[idx] = off;
        g_cur[idx] = off;
        g_csrc[idx] = rsqrtf((float)max(g_degout[idx], 1));
        g_cdst[idx] = rsqrtf((float)max(g_degin[idx], 1));
    }
    if (idx == 0) g_off[NND] = NED;
}

__global__ void fill_kernel(const void* edge) {
    int is64 = g_is64;
    int stride = gridDim.x * blockDim.x;
    for (int e = blockIdx.x * blockDim.x + threadIdx.x; e < NED; e += stride) {
        int s = load_idx(edge, is64, e);
        int d = load_idx(edge, is64, (long long)NED + e);
        int pos = atomicAdd(&g_cur[d], 1);
        g_srcl[pos] = s;
    }
}

// ---------------- W1^T fp16 conversion --------------------------------------
__global__ void convBt_kernel(const float* __restrict__ W1) {
    int i = blockIdx.x * blockDim.x + threadIdx.x;
    if (i >= F1 * KP) return;
    int n = i / KP, k = i % KP;
    float x = (k < F0) ? W1[(size_t)k * F1 + n] : 0.f;
    g_Bt[i] = __float2half_rn(x);
}

// ---------------- GEMM1: fp16 mma.sync, M=128 N=256, 3-stage ----------------
#define ASTR 80
#define SA_SZ (128 * ASTR)        /* 10240 */
#define SB_SZ (256 * ASTR)        /* 20480 */
#define STAGE (SA_SZ + SB_SZ)     /* 30720 */
#define SMEM_G1 (3 * STAGE)       /* 92160 */

extern __shared__ char g1s[];

__global__ __launch_bounds__(512, 1)
void gemm1_f16(const float* __restrict__ A, const __half* __restrict__ Bt,
               __half* __restrict__ C, const float* __restrict__ csrc)
{
    const int tid = threadIdx.x;
    const int l   = tid & 31;
    const int wid = tid >> 5;
    const int mw  = (wid & 1) * 64;
    const int nw  = (wid >> 1) * 32;
    const int bm  = blockIdx.x * 128;
    const uint32_t sb = smem_u32(g1s);

    // A ldg geometry: row = tid>>2 (128 rows), cg = tid&3 -> cols cg*8..+7
    const int a_row = tid >> 2, a_cg = tid & 3;
    const int a_grow = bm + a_row;
    const bool a_rv = (a_grow < NND);
    const float* a_base = A + (size_t)a_grow * F0 + a_cg * 8;

    float acc[4][4][4];
    #pragma unroll
    for (int t = 0; t < 4; t++)
        #pragma unroll
        for (int j = 0; j < 4; j++)
            #pragma unroll
            for (int q = 0; q < 4; q++) acc[t][j][q] = 0.f;

    float rA[8];
    auto ldgA = [&](int kt) {
        int c0 = kt * 32 + a_cg * 8;
        #pragma unroll
        for (int j = 0; j < 8; j++)
            rA[j] = (a_rv && (c0 + j) < F0) ? a_base[kt * 32 + j] : 0.f;
    };
    auto stsA = [&](int buf) {
        uint32_t w0 = pack_h2(rA[0], rA[1]);
        uint32_t w1 = pack_h2(rA[2], rA[3]);
        uint32_t w2 = pack_h2(rA[4], rA[5]);
        uint32_t w3 = pack_h2(rA[6], rA[7]);
        *(uint4*)(g1s + buf * STAGE + a_row * ASTR + a_cg * 16) = make_uint4(w0, w1, w2, w3);
    };
    auto cpB = [&](int kt, int buf) {
        #pragma unroll
        for (int i = 0; i < 2; i++) {
            int ch = tid * 2 + i;                 // 0..1023
            int n = ch >> 2, k16 = ch & 3;
            uint32_t dst = sb + (uint32_t)(buf * STAGE + SA_SZ + n * ASTR + k16 * 16);
            cpa16(dst, Bt + (size_t)n * KP + kt * 32 + k16 * 8);
        }
    };

    // prologue
    ldgA(0); cpB(0, 0); CP_COMMIT();
    stsA(0);
    ldgA(1); cpB(1, 1); CP_COMMIT();

    const int      lrow = ((l >> 3) & 1) * 8 + (l & 7);
    const uint32_t acol = (uint32_t)((l >> 4) * 16);
    const uint32_t brow = (uint32_t)(nw + ((l >> 4) & 1) * 8 + (l & 7));
    const uint32_t bcol = (uint32_t)(((l >> 3) & 1) * 16);

    for (int kt = 0; kt < NKT; kt++) {
        CP_WAIT1();
        __syncthreads();
        if (kt + 1 < NKT) stsA((kt + 1) % 3);
        if (kt + 2 < NKT) { cpB(kt + 2, (kt + 2) % 3); ldgA(kt + 2); }
        CP_COMMIT();

        const int buf = kt % 3;
        const uint32_t sa  = sb + (uint32_t)(buf * STAGE);
        const uint32_t sbb = sa + SA_SZ;

        #pragma unroll
        for (int ks = 0; ks < 2; ks++) {
            uint32_t bb[8];
            uint32_t ba = sbb + brow * ASTR + (uint32_t)(ks * 32) + bcol;
            ldsm4(bb[0], bb[1], bb[2], bb[3], ba);
            ldsm4(bb[4], bb[5], bb[6], bb[7], ba + 16 * ASTR);
            #pragma unroll
            for (int t = 0; t < 4; t++) {
                uint32_t aa[4];
                uint32_t aadr = sa + (uint32_t)((mw + t * 16 + lrow) * ASTR + ks * 32) + acol;
                ldsm4(aa[0], aa[1], aa[2], aa[3], aadr);
                mma_f16(acc[t][0], aa, bb[0], bb[1]);
                mma_f16(acc[t][1], aa, bb[2], bb[3]);
                mma_f16(acc[t][2], aa, bb[4], bb[5]);
                mma_f16(acc[t][3], aa, bb[6], bb[7]);
            }
        }
        __syncthreads();
    }

    // epilogue: * csrc, store fp16
    #pragma unroll
    for (int t = 0; t < 4; t++) {
        int r0 = bm + mw + t * 16 + (l >> 2);
        #pragma unroll
        for (int half = 0; half < 2; half++) {
            int row = r0 + half * 8;
            if (row < NND) {
                float s = csrc[row];
                #pragma unroll
                for (int j = 0; j < 4; j++) {
                    int col = nw + j * 8 + (l & 3) * 2;
                    __half2 v = __floats2half2_rn(acc[t][j][half * 2] * s,
                                                  acc[t][j][half * 2 + 1] * s);
                    *(__half2*)&C[(size_t)row * F1 + col] = v;
                }
            }
        }
    }
}

// ---------------- CSR aggregation, F=256 fp16-in, fused relu ----------------
__global__ __launch_bounds__(256)
void agg256_kernel(const __half* __restrict__ h, float* __restrict__ xo,
                   const float* __restrict__ bias, const float* __restrict__ cdst) {
    int warp = (blockIdx.x * blockDim.x + threadIdx.x) >> 5;
    int lane = threadIdx.x & 31;
    if (warp >= NND) return;
    int i0 = g_off[warp], i1 = g_off[warp + 1];
    float a[8] = {0.f, 0.f, 0.f, 0.f, 0.f, 0.f, 0.f, 0.f};
    for (int i = i0; i < i1; i++) {
        int s = g_srcl[i];
        uint4 v = *(const uint4*)(h + (size_t)s * 256 + lane * 8);
        __half2 h0 = *(__half2*)&v.x, h1 = *(__half2*)&v.y;
        __half2 h2 = *(__half2*)&v.z, h3 = *(__half2*)&v.w;
        float2 f0 = __half22float2(h0), f1 = __half22float2(h1);
        float2 f2 = __half22float2(h2), f3 = __half22float2(h3);
        a[0] += f0.x; a[1] += f0.y; a[2] += f1.x; a[3] += f1.y;
        a[4] += f2.x; a[5] += f2.y; a[6] += f3.x; a[7] += f3.y;
    }
    float c = cdst[warp];
    const float4* bp = (const float4*)bias + lane * 2;
    float4 b0 = bp[0], b1 = bp[1];
    float4 o0, o1;
    o0.x = fmaxf(fmaf(a[0], c, b0.x), 0.f); o0.y = fmaxf(fmaf(a[1], c, b0.y), 0.f);
    o0.z = fmaxf(fmaf(a[2], c, b0.z), 0.f); o0.w = fmaxf(fmaf(a[3], c, b0.w), 0.f);
    o1.x = fmaxf(fmaf(a[4], c, b1.x), 0.f); o1.y = fmaxf(fmaf(a[5], c, b1.y), 0.f);
    o1.z = fmaxf(fmaf(a[6], c, b1.z), 0.f); o1.w = fmaxf(fmaf(a[7], c, b1.w), 0.f);
    float4* op = (float4*)(xo + (size_t)warp * 256) + lane * 2;
    op[0] = o0; op[1] = o1;
}

// ---------------- CSR aggregation, F=32, fused relu -------------------------
__global__ __launch_bounds__(256)
void agg32_kernel(const float* __restrict__ h, float* __restrict__ xo,
                  const float* __restrict__ bias, const float* __restrict__ cdst) {
    int warp = (blockIdx.x * blockDim.x + threadIdx.x) >> 5;
    int lane = threadIdx.x & 31;
    if (warp >= NND) return;
    int i0 = g_off[warp], i1 = g_off[warp + 1];
    float a0 = 0.f, a1 = 0.f, a2 = 0.f, a3 = 0.f;
    int i = i0;
    for (; i + 4 <= i1; i += 4) {
        int s0 = g_srcl[i], s1 = g_srcl[i + 1], s2 = g_srcl[i + 2], s3 = g_srcl[i + 3];
        a0 += h[(size_t)s0 * 32 + lane];
        a1 += h[(size_t)s1 * 32 + lane];
        a2 += h[(size_t)s2 * 32 + lane];
        a3 += h[(size_t)s3 * 32 + lane];
    }
    for (; i < i1; i++) a0 += h[(size_t)g_srcl[i] * 32 + lane];
    float a = (a0 + a1) + (a2 + a3);
    xo[(size_t)warp * 32 + lane] = fmaxf(fmaf(a, cdst[warp], bias[lane]), 0.f);
}

// ---------------- CSR aggregation F=7 + log_softmax -------------------------
__global__ __launch_bounds__(256)
void agg7_final_kernel(const float* __restrict__ h, const float* __restrict__ b3,
                       const float* __restrict__ cdst, float* __restrict__ out) {
    int warp = (blockIdx.x * blockDim.x + threadIdx.x) >> 5;
    int lane = threadIdx.x & 31;
    int sub  = lane & 7;
    int node = warp * 4 + (lane >> 3);
    if (node >= NND) return;
    int i0 = g_off[node], i1 = g_off[node + 1];
    float a = 0.f;
    if (sub < 7)
        for (int i = i0; i < i1; i++) a += h[(size_t)g_srcl[i] * 8 + sub];
    float v = (sub < 7) ? fmaf(a, cdst[node], b3[sub]) : -1e30f;
    float mx = v;
    #pragma unroll
    for (int d = 1; d < 8; d <<= 1)
        mx = fmaxf(mx, __shfl_xor_sync(0xFFFFFFFFu, mx, d));
    float e = (sub < 7) ? expf(v - mx) : 0.f;
    float se = e;
    #pragma unroll
    for (int d = 1; d < 8; d <<= 1)
        se += __shfl_xor_sync(0xFFFFFFFFu, se, d);
    float lse = logf(se);
    if (sub < 7) out[(size_t)node * 7 + sub] = v - mx - lse;
}

// ---------------- GEMM2: [50000,256] @ [256,32], * c_src --------------------
__global__ __launch_bounds__(1024)
void gemm2_kernel(const float* __restrict__ x1, const float* __restrict__ W2,
                  float* __restrict__ h2, const float* __restrict__ csrc) {
    __shared__ float Ws[256 * 32];
    int tid = threadIdx.x;
    for (int i = tid; i < 256 * 32; i += 1024) Ws[i] = W2[i];
    __syncthreads();
    int m = blockIdx.x * 32 + (tid >> 5);
    int c = tid & 31;
    if (m >= NND) return;
    const float4* xr = (const float4*)(x1 + (size_t)m * 256);
    float acc = 0.f;
    #pragma unroll
    for (int k4 = 0; k4 < 64; k4++) {
        float4 x = xr[k4];
        int k = k4 * 4;
        acc = fmaf(x.x, Ws[(k + 0) * 32 + c], acc);
        acc = fmaf(x.y, Ws[(k + 1) * 32 + c], acc);
        acc = fmaf(x.z, Ws[(k + 2) * 32 + c], acc);
        acc = fmaf(x.w, Ws[(k + 3) * 32 + c], acc);
    }
    h2[(size_t)m * 32 + c] = acc * csrc[m];
}

// ---------------- GEMM3: [50000,32] @ [32,7], * c_src (stride-8 out) --------
__global__ void gemm3_kernel(const float* __restrict__ x2, const float* __restrict__ W3,
                             float* __restrict__ h3, const float* __restrict__ csrc) {
    __shared__ float Ws[32 * 7];
    int tid = threadIdx.x;
    if (tid < 224) Ws[tid] = W3[tid];
    __syncthreads();
    int m = blockIdx.x * blockDim.x + tid;
    if (m >= NND) return;
    const float4* xr = (const float4*)(x2 + (size_t)m * 32);
    float x[32];
    #pragma unroll
    for (int i = 0; i < 8; i++) {
        float4 v = xr[i];
        x[4 * i] = v.x; x[4 * i + 1] = v.y; x[4 * i + 2] = v.z; x[4 * i + 3] = v.w;
    }
    float s = csrc[m];
    #pragma unroll
    for (int j = 0; j < 7; j++) {
        float a = 0.f;
        #pragma unroll
        for (int k = 0; k < 32; k++) a = fmaf(x[k], Ws[k * 7 + j], a);
        h3[(size_t)m * 8 + j] = a * s;
    }
}

// ---------------- host ------------------------------------------------------
extern "C" void kernel_launch(void* const* d_in, const int* in_sizes, int n_in,
                              void* d_out, int out_size) {
    const float* feat = (const float*)d_in[0];
    const void*  edge = d_in[1];
    const float* W1   = (const float*)d_in[2];
    const float* b1   = (const float*)d_in[3];
    const float* W2   = (const float*)d_in[4];
    const float* b2   = (const float*)d_in[5];
    const float* W3   = (const float*)d_in[6];
    const float* b3   = (const float*)d_in[7];
    float* out = (float*)d_out;

    float *p_csrc, *p_cdst, *p_x1, *p_h2, *p_x2, *p_h3;
    __half *p_h1, *p_Bt;
    cudaGetSymbolAddress((void**)&p_csrc, g_csrc);
    cudaGetSymbolAddress((void**)&p_cdst, g_cdst);
    cudaGetSymbolAddress((void**)&p_h1,   g_h1);
    cudaGetSymbolAddress((void**)&p_x1,   g_x1);
    cudaGetSymbolAddress((void**)&p_h2,   g_h2);
    cudaGetSymbolAddress((void**)&p_x2,   g_x2);
    cudaGetSymbolAddress((void**)&p_h3,   g_h3);
    cudaGetSymbolAddress((void**)&p_Bt,   g_Bt);

    static int smem_set = 0;
    if (!smem_set) {
        cudaFuncSetAttribute(gemm1_f16, cudaFuncAttributeMaxDynamicSharedMemorySize, SMEM_G1);
        smem_set = 1;
    }

    init_kernel<<<(NND + 255) / 256, 256>>>(edge);
    deg_kernel<<<1024, 256>>>(edge);
    scanA_kernel<<<NBS, 256>>>();
    scanB_kernel<<<1, 256>>>();
    scanC_kernel<<<NBS, 256>>>();
    fill_kernel<<<1024, 256>>>(edge);
    convBt_kernel<<<(F1 * KP + 255) / 256, 256>>>(W1);

    // Layer 1 (fp16 mma.sync)
    gemm1_f16<<<(NND + 127) / 128, 512, SMEM_G1>>>(feat, p_Bt, p_h1, p_csrc);
    agg256_kernel<<<(NND * 32 + 255) / 256, 256>>>(p_h1, p_x1, b1, p_cdst);

    // Layer 2
    gemm2_kernel<<<(NND + 31) / 32, 1024>>>(p_x1, W2, p_h2, p_csrc);
    agg32_kernel<<<(NND * 32 + 255) / 256, 256>>>(p_h2, p_x2, b2, p_cdst);

    // Layer 3
    gemm3_kernel<<<(NND + 255) / 256, 256>>>(p_x2, W3, p_h3, p_csrc);
    agg7_final_kernel<<<((NND + 3) / 4 * 32 + 255) / 256, 256>>>(p_h3, b3, p_cdst, out);
}

// round 8
// speedup vs baseline: 4.0776x; 1.0824x over previous
#include <cuda_runtime.h>
#include <cuda_fp16.h>
#include <cstdint>
#include <cstddef>

#define NND 50000
#define NED 800000
#define F0 1433
#define KP 1440            // 45 * 32
#define NKT 45
#define F1 256
#define F2 32
#define NBS 196            // scan blocks: 196*256 = 50176

// ---------------- device scratch -------------------------------------------
__device__ float g_csrc[NND];
__device__ float g_cdst[NND];
__device__ __half g_h1[(size_t)NND * F1];
__device__ __half g_h2[(size_t)NND * F2];
__device__ float g_h3[(size_t)NND * 8];
__device__ int   g_is64;
__device__ int   g_degin[NND];
__device__ int   g_degout[NND];
__device__ int   g_off[NND + 1];
__device__ int   g_cur[NND];
__device__ int   g_srcl[NED];
__device__ int   g_bsum[NBS];
// W1^T as fp16: [n=256][k=KP]
__device__ __half g_Bt[(size_t)F1 * KP];

// ---------------- helpers ---------------------------------------------------
__device__ __forceinline__ int load_idx(const void* edge, int is64, long long lin) {
    if (is64) return (int)((const long long*)edge)[lin];
    return ((const int*)edge)[lin];
}
__device__ __forceinline__ void cpa16(uint32_t dst, const void* src) {
    asm volatile("cp.async.cg.shared.global [%0],[%1],16;" :: "r"(dst), "l"(src));
}
#define CP_COMMIT() asm volatile("cp.async.commit_group;")
#define CP_WAIT1()  asm volatile("cp.async.wait_group 1;" ::: "memory")

__device__ __forceinline__ void ldsm4(uint32_t& r0, uint32_t& r1, uint32_t& r2, uint32_t& r3, uint32_t a) {
    asm volatile("ldmatrix.sync.aligned.m8n8.x4.shared.b16 {%0,%1,%2,%3},[%4];"
                 : "=r"(r0), "=r"(r1), "=r"(r2), "=r"(r3) : "r"(a));
}
__device__ __forceinline__ void mma_f16(float* c, const uint32_t* a, uint32_t b0, uint32_t b1) {
    asm volatile("mma.sync.aligned.m16n8k16.row.col.f32.f16.f16.f32 "
                 "{%0,%1,%2,%3},{%4,%5,%6,%7},{%8,%9},{%0,%1,%2,%3};"
                 : "+f"(c[0]), "+f"(c[1]), "+f"(c[2]), "+f"(c[3])
                 : "r"(a[0]), "r"(a[1]), "r"(a[2]), "r"(a[3]), "r"(b0), "r"(b1));
}
__device__ __forceinline__ uint32_t smem_u32(const void* p) {
    uint32_t a;
    asm("{ .reg .u64 t; cvta.to.shared.u64 t, %1; cvt.u32.u64 %0, t; }" : "=r"(a) : "l"(p));
    return a;
}
__device__ __forceinline__ uint32_t pack_h2(float a, float b) {
    __half2 h = __floats2half2_rn(a, b);
    return *(uint32_t*)&h;
}

// ---------------- init: detect + zero degrees + convert W1^T ----------------
__global__ void init_kernel(const void* edge, const float* __restrict__ W1) {
    int i = blockIdx.x * blockDim.x + threadIdx.x;
    if (i == 0) {
        const unsigned long long* p = (const unsigned long long*)edge;
        int ok = 1;
        #pragma unroll
        for (int j = 0; j < 16; j++)
            if (p[j] >= (unsigned long long)NND) ok = 0;
        g_is64 = ok;
    }
    if (i < NND) { g_degin[i] = 0; g_degout[i] = 0; }
    if (i < F1 * KP) {
        int n = i / KP, k = i % KP;
        float x = (k < F0) ? W1[(size_t)k * F1 + n] : 0.f;
        g_Bt[i] = __float2half_rn(x);
    }
}

__global__ void deg_kernel(const void* edge) {
    int is64 = g_is64;
    int stride = gridDim.x * blockDim.x;
    for (int e = blockIdx.x * blockDim.x + threadIdx.x; e < NED; e += stride) {
        int s = load_idx(edge, is64, e);
        int d = load_idx(edge, is64, (long long)NED + e);
        atomicAdd(&g_degout[s], 1);
        atomicAdd(&g_degin[d], 1);
    }
}

// ---------------- 2-kernel coalesced scan -----------------------------------
__global__ __launch_bounds__(256) void scanA_kernel() {
    __shared__ int sd[256];
    int t = threadIdx.x, b = blockIdx.x;
    int idx = b * 256 + t;
    int d = (idx < NND) ? g_degin[idx] : 0;
    sd[t] = d; __syncthreads();
    #pragma unroll
    for (int s = 1; s < 256; s <<= 1) {
        int v = (t >= s) ? sd[t - s] : 0;
        __syncthreads();
        sd[t] += v;
        __syncthreads();
    }
    if (idx < NND) g_off[idx] = sd[t] - d;     // block-exclusive
    if (t == 255) g_bsum[b] = sd[255];
}
__global__ __launch_bounds__(256) void scanC_kernel() {
    __shared__ int sd[256];
    int t = threadIdx.x, b = blockIdx.x;
    sd[t] = (t < b) ? g_bsum[t] : 0;           // b <= NBS-1 < 256
    __syncthreads();
    #pragma unroll
    for (int s = 128; s > 0; s >>= 1) {
        if (t < s) sd[t] += sd[t + s];
        __syncthreads();
    }
    int pre = sd[0];
    int idx = b * 256 + t;
    if (idx < NND) {
        int off = g_off[idx] + pre;
        g_off[idx] = off;
        g_cur[idx] = off;
        g_csrc[idx] = rsqrtf((float)max(g_degout[idx], 1));
        g_cdst[idx] = rsqrtf((float)max(g_degin[idx], 1));
    }
    if (idx == 0) g_off[NND] = NED;
}

__global__ void fill_kernel(const void* edge) {
    int is64 = g_is64;
    int stride = gridDim.x * blockDim.x;
    for (int e = blockIdx.x * blockDim.x + threadIdx.x; e < NED; e += stride) {
        int s = load_idx(edge, is64, e);
        int d = load_idx(edge, is64, (long long)NED + e);
        int pos = atomicAdd(&g_cur[d], 1);
        g_srcl[pos] = s;
    }
}

// ---------------- GEMM1: fp16 mma.sync, M=128 N=256, 3-stage ----------------
#define ASTR 80
#define SA_SZ (128 * ASTR)        /* 10240 */
#define SB_SZ (256 * ASTR)        /* 20480 */
#define STAGE (SA_SZ + SB_SZ)     /* 30720 */
#define SMEM_G1 (3 * STAGE)       /* 92160 */

extern __shared__ char g1s[];

__global__ __launch_bounds__(512, 1)
void gemm1_f16(const float* __restrict__ A, const __half* __restrict__ Bt,
               __half* __restrict__ C, const float* __restrict__ csrc)
{
    const int tid = threadIdx.x;
    const int l   = tid & 31;
    const int wid = tid >> 5;
    const int mw  = (wid & 1) * 64;
    const int nw  = (wid >> 1) * 32;
    const int bm  = blockIdx.x * 128;
    const uint32_t sb = smem_u32(g1s);

    const int a_row = tid >> 2, a_cg = tid & 3;
    const int a_grow = bm + a_row;
    const bool a_rv = (a_grow < NND);
    const float* a_base = A + (size_t)a_grow * F0 + a_cg * 8;

    float acc[4][4][4];
    #pragma unroll
    for (int t = 0; t < 4; t++)
        #pragma unroll
        for (int j = 0; j < 4; j++)
            #pragma unroll
            for (int q = 0; q < 4; q++) acc[t][j][q] = 0.f;

    float rA[8];
    auto ldgA = [&](int kt) {
        int c0 = kt * 32 + a_cg * 8;
        #pragma unroll
        for (int j = 0; j < 8; j++)
            rA[j] = (a_rv && (c0 + j) < F0) ? a_base[kt * 32 + j] : 0.f;
    };
    auto stsA = [&](int buf) {
        uint32_t w0 = pack_h2(rA[0], rA[1]);
        uint32_t w1 = pack_h2(rA[2], rA[3]);
        uint32_t w2 = pack_h2(rA[4], rA[5]);
        uint32_t w3 = pack_h2(rA[6], rA[7]);
        *(uint4*)(g1s + buf * STAGE + a_row * ASTR + a_cg * 16) = make_uint4(w0, w1, w2, w3);
    };
    auto cpB = [&](int kt, int buf) {
        #pragma unroll
        for (int i = 0; i < 2; i++) {
            int ch = tid * 2 + i;
            int n = ch >> 2, k16 = ch & 3;
            uint32_t dst = sb + (uint32_t)(buf * STAGE + SA_SZ + n * ASTR + k16 * 16);
            cpa16(dst, Bt + (size_t)n * KP + kt * 32 + k16 * 8);
        }
    };

    ldgA(0); cpB(0, 0); CP_COMMIT();
    stsA(0);
    ldgA(1); cpB(1, 1); CP_COMMIT();

    const int      lrow = ((l >> 3) & 1) * 8 + (l & 7);
    const uint32_t acol = (uint32_t)((l >> 4) * 16);
    const uint32_t brow = (uint32_t)(nw + ((l >> 4) & 1) * 8 + (l & 7));
    const uint32_t bcol = (uint32_t)(((l >> 3) & 1) * 16);

    for (int kt = 0; kt < NKT; kt++) {
        CP_WAIT1();
        __syncthreads();
        if (kt + 1 < NKT) stsA((kt + 1) % 3);
        if (kt + 2 < NKT) { cpB(kt + 2, (kt + 2) % 3); ldgA(kt + 2); }
        CP_COMMIT();

        const int buf = kt % 3;
        const uint32_t sa  = sb + (uint32_t)(buf * STAGE);
        const uint32_t sbb = sa + SA_SZ;

        #pragma unroll
        for (int ks = 0; ks < 2; ks++) {
            uint32_t bb[8];
            uint32_t ba = sbb + brow * ASTR + (uint32_t)(ks * 32) + bcol;
            ldsm4(bb[0], bb[1], bb[2], bb[3], ba);
            ldsm4(bb[4], bb[5], bb[6], bb[7], ba + 16 * ASTR);
            #pragma unroll
            for (int t = 0; t < 4; t++) {
                uint32_t aa[4];
                uint32_t aadr = sa + (uint32_t)((mw + t * 16 + lrow) * ASTR + ks * 32) + acol;
                ldsm4(aa[0], aa[1], aa[2], aa[3], aadr);
                mma_f16(acc[t][0], aa, bb[0], bb[1]);
                mma_f16(acc[t][1], aa, bb[2], bb[3]);
                mma_f16(acc[t][2], aa, bb[4], bb[5]);
                mma_f16(acc[t][3], aa, bb[6], bb[7]);
            }
        }
        __syncthreads();
    }

    #pragma unroll
    for (int t = 0; t < 4; t++) {
        int r0 = bm + mw + t * 16 + (l >> 2);
        #pragma unroll
        for (int half = 0; half < 2; half++) {
            int row = r0 + half * 8;
            if (row < NND) {
                float s = csrc[row];
                #pragma unroll
                for (int j = 0; j < 4; j++) {
                    int col = nw + j * 8 + (l & 3) * 2;
                    __half2 v = __floats2half2_rn(acc[t][j][half * 2] * s,
                                                  acc[t][j][half * 2 + 1] * s);
                    *(__half2*)&C[(size_t)row * F1 + col] = v;
                }
            }
        }
    }
}

// ---------------- fusedA: agg256(h1 fp16) + relu + GEMM2 -> h2 fp16 ---------
// 1024 threads = 32 warps = 32 nodes per block
__global__ __launch_bounds__(1024)
void fusedA_kernel(const __half* __restrict__ h1, const float* __restrict__ W2,
                   const float* __restrict__ b1, __half* __restrict__ h2,
                   const float* __restrict__ csrc, const float* __restrict__ cdst) {
    __shared__ float W2s[256 * 32];     // 32 KB
    __shared__ float x1s[32][256];      // 32 KB
    const int tid = threadIdx.x;
    for (int i = tid; i < 256 * 32; i += 1024) W2s[i] = W2[i];
    __syncthreads();

    const int wl   = tid >> 5;                     // warp in block
    const int lane = tid & 31;
    const int node = blockIdx.x * 32 + wl;
    if (node >= NND) return;                       // no __syncthreads after this

    int i0 = g_off[node], i1 = g_off[node + 1];
    float a[8] = {0.f, 0.f, 0.f, 0.f, 0.f, 0.f, 0.f, 0.f};
    int i = i0;
    for (; i + 2 <= i1; i += 2) {
        int s0 = g_srcl[i], s1 = g_srcl[i + 1];
        uint4 v0 = *(const uint4*)(h1 + (size_t)s0 * 256 + lane * 8);
        uint4 v1 = *(const uint4*)(h1 + (size_t)s1 * 256 + lane * 8);
        float2 f;
        f = __half22float2(*(__half2*)&v0.x); a[0] += f.x; a[1] += f.y;
        f = __half22float2(*(__half2*)&v0.y); a[2] += f.x; a[3] += f.y;
        f = __half22float2(*(__half2*)&v0.z); a[4] += f.x; a[5] += f.y;
        f = __half22float2(*(__half2*)&v0.w); a[6] += f.x; a[7] += f.y;
        f = __half22float2(*(__half2*)&v1.x); a[0] += f.x; a[1] += f.y;
        f = __half22float2(*(__half2*)&v1.y); a[2] += f.x; a[3] += f.y;
        f = __half22float2(*(__half2*)&v1.z); a[4] += f.x; a[5] += f.y;
        f = __half22float2(*(__half2*)&v1.w); a[6] += f.x; a[7] += f.y;
    }
    if (i < i1) {
        int s0 = g_srcl[i];
        uint4 v0 = *(const uint4*)(h1 + (size_t)s0 * 256 + lane * 8);
        float2 f;
        f = __half22float2(*(__half2*)&v0.x); a[0] += f.x; a[1] += f.y;
        f = __half22float2(*(__half2*)&v0.y); a[2] += f.x; a[3] += f.y;
        f = __half22float2(*(__half2*)&v0.z); a[4] += f.x; a[5] += f.y;
        f = __half22float2(*(__half2*)&v0.w); a[6] += f.x; a[7] += f.y;
    }
    // x1 = relu(a * cdst + b1) -> smem
    {
        float c = cdst[node];
        const float4* bp = (const float4*)b1 + lane * 2;
        float4 b0 = bp[0], b1v = bp[1];
        float4 o0, o1;
        o0.x = fmaxf(fmaf(a[0], c, b0.x), 0.f);  o0.y = fmaxf(fmaf(a[1], c, b0.y), 0.f);
        o0.z = fmaxf(fmaf(a[2], c, b0.z), 0.f);  o0.w = fmaxf(fmaf(a[3], c, b0.w), 0.f);
        o1.x = fmaxf(fmaf(a[4], c, b1v.x), 0.f); o1.y = fmaxf(fmaf(a[5], c, b1v.y), 0.f);
        o1.z = fmaxf(fmaf(a[6], c, b1v.z), 0.f); o1.w = fmaxf(fmaf(a[7], c, b1v.w), 0.f);
        *(float4*)&x1s[wl][lane * 8]     = o0;
        *(float4*)&x1s[wl][lane * 8 + 4] = o1;
    }
    __syncwarp();
    // gemm2: out col = lane
    float acc = 0.f;
    const float* xr = x1s[wl];
    #pragma unroll
    for (int k4 = 0; k4 < 64; k4++) {
        float4 x = *(const float4*)&xr[k4 * 4];
        int k = k4 * 4;
        acc = fmaf(x.x, W2s[(k + 0) * 32 + lane], acc);
        acc = fmaf(x.y, W2s[(k + 1) * 32 + lane], acc);
        acc = fmaf(x.z, W2s[(k + 2) * 32 + lane], acc);
        acc = fmaf(x.w, W2s[(k + 3) * 32 + lane], acc);
    }
    h2[(size_t)node * 32 + lane] = __float2half_rn(acc * csrc[node]);
}

// ---------------- fusedB: agg32(h2 fp16) + relu + GEMM3 -> h3 ---------------
__global__ __launch_bounds__(256)
void fusedB_kernel(const __half* __restrict__ h2, const float* __restrict__ W3,
                   const float* __restrict__ b2, float* __restrict__ h3,
                   const float* __restrict__ csrc, const float* __restrict__ cdst) {
    __shared__ float W3s[224];
    const int tid = threadIdx.x;
    if (tid < 224) W3s[tid] = W3[tid];
    __syncthreads();
    const int lane = tid & 31;
    const int node = (blockIdx.x * 256 + tid) >> 5;
    if (node >= NND) return;
    int i0 = g_off[node], i1 = g_off[node + 1];
    float a0 = 0.f, a1 = 0.f, a2 = 0.f, a3 = 0.f;
    int i = i0;
    for (; i + 4 <= i1; i += 4) {
        a0 += __half2float(h2[(size_t)g_srcl[i]     * 32 + lane]);
        a1 += __half2float(h2[(size_t)g_srcl[i + 1] * 32 + lane]);
        a2 += __half2float(h2[(size_t)g_srcl[i + 2] * 32 + lane]);
        a3 += __half2float(h2[(size_t)g_srcl[i + 3] * 32 + lane]);
    }
    for (; i < i1; i++) a0 += __half2float(h2[(size_t)g_srcl[i] * 32 + lane]);
    float x2 = fmaxf(fmaf((a0 + a1) + (a2 + a3), cdst[node], b2[lane]), 0.f);
    float s = csrc[node];
    float r[7];
    #pragma unroll
    for (int j = 0; j < 7; j++) {
        float v = x2 * W3s[lane * 7 + j];
        #pragma unroll
        for (int d = 16; d > 0; d >>= 1)
            v += __shfl_xor_sync(0xFFFFFFFFu, v, d);
        r[j] = v;
    }
    float outv = 0.f;
    #pragma unroll
    for (int j = 0; j < 7; j++) if (lane == j) outv = r[j];
    if (lane < 7) h3[(size_t)node * 8 + lane] = outv * s;
}

// ---------------- CSR aggregation F=7 + log_softmax -------------------------
__global__ __launch_bounds__(256)
void agg7_final_kernel(const float* __restrict__ h, const float* __restrict__ b3,
                       const float* __restrict__ cdst, float* __restrict__ out) {
    int warp = (blockIdx.x * blockDim.x + threadIdx.x) >> 5;
    int lane = threadIdx.x & 31;
    int sub  = lane & 7;
    int node = warp * 4 + (lane >> 3);
    if (node >= NND) return;
    int i0 = g_off[node], i1 = g_off[node + 1];
    float a = 0.f;
    if (sub < 7)
        for (int i = i0; i < i1; i++) a += h[(size_t)g_srcl[i] * 8 + sub];
    float v = (sub < 7) ? fmaf(a, cdst[node], b3[sub]) : -1e30f;
    float mx = v;
    #pragma unroll
    for (int d = 1; d < 8; d <<= 1)
        mx = fmaxf(mx, __shfl_xor_sync(0xFFFFFFFFu, mx, d));
    float e = (sub < 7) ? expf(v - mx) : 0.f;
    float se = e;
    #pragma unroll
    for (int d = 1; d < 8; d <<= 1)
        se += __shfl_xor_sync(0xFFFFFFFFu, se, d);
    float lse = logf(se);
    if (sub < 7) out[(size_t)node * 7 + sub] = v - mx - lse;
}

// ---------------- host ------------------------------------------------------
extern "C" void kernel_launch(void* const* d_in, const int* in_sizes, int n_in,
                              void* d_out, int out_size) {
    const float* feat = (const float*)d_in[0];
    const void*  edge = d_in[1];
    const float* W1   = (const float*)d_in[2];
    const float* b1   = (const float*)d_in[3];
    const float* W2   = (const float*)d_in[4];
    const float* b2   = (const float*)d_in[5];
    const float* W3   = (const float*)d_in[6];
    const float* b3   = (const float*)d_in[7];
    float* out = (float*)d_out;

    float *p_csrc, *p_cdst, *p_h3;
    __half *p_h1, *p_h2, *p_Bt;
    cudaGetSymbolAddress((void**)&p_csrc, g_csrc);
    cudaGetSymbolAddress((void**)&p_cdst, g_cdst);
    cudaGetSymbolAddress((void**)&p_h1,   g_h1);
    cudaGetSymbolAddress((void**)&p_h2,   g_h2);
    cudaGetSymbolAddress((void**)&p_h3,   g_h3);
    cudaGetSymbolAddress((void**)&p_Bt,   g_Bt);

    static int smem_set = 0;
    if (!smem_set) {
        cudaFuncSetAttribute(gemm1_f16, cudaFuncAttributeMaxDynamicSharedMemorySize, SMEM_G1);
        smem_set = 1;
    }

    init_kernel<<<(F1 * KP + 255) / 256, 256>>>(edge, W1);
    deg_kernel<<<1024, 256>>>(edge);
    scanA_kernel<<<NBS, 256>>>();
    scanC_kernel<<<NBS, 256>>>();
    fill_kernel<<<1024, 256>>>(edge);

    gemm1_f16<<<(NND + 127) / 128, 512, SMEM_G1>>>(feat, p_Bt, p_h1, p_csrc);
    fusedA_kernel<<<(NND + 31) / 32, 1024>>>(p_h1, W2, b1, p_h2, p_csrc, p_cdst);
    fusedB_kernel<<<(NND * 32 + 255) / 256, 256>>>(p_h2, W3, b2, p_h3, p_csrc, p_cdst);
    agg7_final_kernel<<<((NND + 3) / 4 * 32 + 255) / 256, 256>>>(p_h3, b3, p_cdst, out);
}

// round 9
// speedup vs baseline: 4.4797x; 1.0986x over previous
#include <cuda_runtime.h>
#include <cuda_fp16.h>
#include <cstdint>
#include <cstddef>

#define NND 50000
#define NED 800000
#define F0 1433
#define KP 1440            // 45 * 32
#define NKT 45
#define F1 256
#define F2 32
#define NBS 196            // scan blocks: 196*256 = 50176

// ---------------- device scratch -------------------------------------------
__device__ float g_csrc[NND];
__device__ float g_cdst[NND];
__device__ __half g_h1[(size_t)NND * F1];
__device__ __half g_h2[(size_t)NND * F2];
__device__ float g_h3[(size_t)NND * 8];
__device__ int   g_is64;
__device__ int   g_degin[NND];
__device__ int   g_degout[NND];
__device__ int   g_off[NND + 1];
__device__ int   g_cur[NND];
__device__ int   g_srcl[NED];
__device__ int   g_bsum[NBS];
// W1^T as fp16: [n=256][k=KP]
__device__ __half g_Bt[(size_t)F1 * KP];

// ---------------- helpers ---------------------------------------------------
__device__ __forceinline__ int load_idx(const void* edge, int is64, long long lin) {
    if (is64) return (int)((const long long*)edge)[lin];
    return ((const int*)edge)[lin];
}
__device__ __forceinline__ void cpa16(uint32_t dst, const void* src) {
    asm volatile("cp.async.cg.shared.global [%0],[%1],16;" :: "r"(dst), "l"(src));
}
#define CP_COMMIT() asm volatile("cp.async.commit_group;")
#define CP_WAIT1()  asm volatile("cp.async.wait_group 1;" ::: "memory")

__device__ __forceinline__ void ldsm4(uint32_t& r0, uint32_t& r1, uint32_t& r2, uint32_t& r3, uint32_t a) {
    asm volatile("ldmatrix.sync.aligned.m8n8.x4.shared.b16 {%0,%1,%2,%3},[%4];"
                 : "=r"(r0), "=r"(r1), "=r"(r2), "=r"(r3) : "r"(a));
}
__device__ __forceinline__ void mma_f16(float* c, const uint32_t* a, uint32_t b0, uint32_t b1) {
    asm volatile("mma.sync.aligned.m16n8k16.row.col.f32.f16.f16.f32 "
                 "{%0,%1,%2,%3},{%4,%5,%6,%7},{%8,%9},{%0,%1,%2,%3};"
                 : "+f"(c[0]), "+f"(c[1]), "+f"(c[2]), "+f"(c[3])
                 : "r"(a[0]), "r"(a[1]), "r"(a[2]), "r"(a[3]), "r"(b0), "r"(b1));
}
__device__ __forceinline__ uint32_t smem_u32(const void* p) {
    uint32_t a;
    asm("{ .reg .u64 t; cvta.to.shared.u64 t, %1; cvt.u32.u64 %0, t; }" : "=r"(a) : "l"(p));
    return a;
}
__device__ __forceinline__ uint32_t pack_h2(float a, float b) {
    __half2 h = __floats2half2_rn(a, b);
    return *(uint32_t*)&h;
}

// ---------------- init: detect + zero degrees + convert W1^T ----------------
__global__ void init_kernel(const void* edge, const float* __restrict__ W1) {
    int i = blockIdx.x * blockDim.x + threadIdx.x;
    if (i == 0) {
        const unsigned long long* p = (const unsigned long long*)edge;
        int ok = 1;
        #pragma unroll
        for (int j = 0; j < 16; j++)
            if (p[j] >= (unsigned long long)NND) ok = 0;
        g_is64 = ok;
    }
    if (i < NND) { g_degin[i] = 0; g_degout[i] = 0; }
    if (i < F1 * KP) {
        int n = i / KP, k = i % KP;
        float x = (k < F0) ? W1[(size_t)k * F1 + n] : 0.f;
        g_Bt[i] = __float2half_rn(x);
    }
}

__global__ void deg_kernel(const void* edge) {
    int is64 = g_is64;
    int stride = gridDim.x * blockDim.x;
    for (int e = blockIdx.x * blockDim.x + threadIdx.x; e < NED; e += stride) {
        int s = load_idx(edge, is64, e);
        int d = load_idx(edge, is64, (long long)NED + e);
        atomicAdd(&g_degout[s], 1);
        atomicAdd(&g_degin[d], 1);
    }
}

// ---------------- 2-kernel coalesced scan -----------------------------------
__global__ __launch_bounds__(256) void scanA_kernel() {
    __shared__ int sd[256];
    int t = threadIdx.x, b = blockIdx.x;
    int idx = b * 256 + t;
    int d = (idx < NND) ? g_degin[idx] : 0;
    sd[t] = d; __syncthreads();
    #pragma unroll
    for (int s = 1; s < 256; s <<= 1) {
        int v = (t >= s) ? sd[t - s] : 0;
        __syncthreads();
        sd[t] += v;
        __syncthreads();
    }
    if (idx < NND) g_off[idx] = sd[t] - d;     // block-exclusive
    if (t == 255) g_bsum[b] = sd[255];
}
__global__ __launch_bounds__(256) void scanC_kernel() {
    __shared__ int sd[256];
    int t = threadIdx.x, b = blockIdx.x;
    sd[t] = (t < b) ? g_bsum[t] : 0;
    __syncthreads();
    #pragma unroll
    for (int s = 128; s > 0; s >>= 1) {
        if (t < s) sd[t] += sd[t + s];
        __syncthreads();
    }
    int pre = sd[0];
    int idx = b * 256 + t;
    if (idx < NND) {
        int off = g_off[idx] + pre;
        g_off[idx] = off;
        g_cur[idx] = off;
        g_csrc[idx] = rsqrtf((float)max(g_degout[idx], 1));
        g_cdst[idx] = rsqrtf((float)max(g_degin[idx], 1));
    }
    if (idx == 0) g_off[NND] = NED;
}

__global__ void fill_kernel(const void* edge) {
    int is64 = g_is64;
    int stride = gridDim.x * blockDim.x;
    for (int e = blockIdx.x * blockDim.x + threadIdx.x; e < NED; e += stride) {
        int s = load_idx(edge, is64, e);
        int d = load_idx(edge, is64, (long long)NED + e);
        int pos = atomicAdd(&g_cur[d], 1);
        g_srcl[pos] = s;
    }
}

// ---------------- GEMM1: fp16 mma.sync, M=128 N=256, 3-stage ----------------
// NOTE: csrc scaling moved to fusedA gather; gemm1 depends only on feat + g_Bt.
#define ASTR 80
#define SA_SZ (128 * ASTR)        /* 10240 */
#define SB_SZ (256 * ASTR)        /* 20480 */
#define STAGE (SA_SZ + SB_SZ)     /* 30720 */
#define SMEM_G1 (3 * STAGE)       /* 92160 */

extern __shared__ char g1s[];

__global__ __launch_bounds__(512, 1)
void gemm1_f16(const float* __restrict__ A, const __half* __restrict__ Bt,
               __half* __restrict__ C)
{
    const int tid = threadIdx.x;
    const int l   = tid & 31;
    const int wid = tid >> 5;
    const int mw  = (wid & 1) * 64;
    const int nw  = (wid >> 1) * 32;
    const int bm  = blockIdx.x * 128;
    const uint32_t sb = smem_u32(g1s);

    const int a_row = tid >> 2, a_cg = tid & 3;
    const int a_grow = bm + a_row;
    const bool a_rv = (a_grow < NND);
    const float* a_base = A + (size_t)a_grow * F0 + a_cg * 8;

    float acc[4][4][4];
    #pragma unroll
    for (int t = 0; t < 4; t++)
        #pragma unroll
        for (int j = 0; j < 4; j++)
            #pragma unroll
            for (int q = 0; q < 4; q++) acc[t][j][q] = 0.f;

    float rA[8];
    auto ldgA = [&](int kt) {
        int c0 = kt * 32 + a_cg * 8;
        #pragma unroll
        for (int j = 0; j < 8; j++)
            rA[j] = (a_rv && (c0 + j) < F0) ? a_base[kt * 32 + j] : 0.f;
    };
    auto stsA = [&](int buf) {
        uint32_t w0 = pack_h2(rA[0], rA[1]);
        uint32_t w1 = pack_h2(rA[2], rA[3]);
        uint32_t w2 = pack_h2(rA[4], rA[5]);
        uint32_t w3 = pack_h2(rA[6], rA[7]);
        *(uint4*)(g1s + buf * STAGE + a_row * ASTR + a_cg * 16) = make_uint4(w0, w1, w2, w3);
    };
    auto cpB = [&](int kt, int buf) {
        #pragma unroll
        for (int i = 0; i < 2; i++) {
            int ch = tid * 2 + i;
            int n = ch >> 2, k16 = ch & 3;
            uint32_t dst = sb + (uint32_t)(buf * STAGE + SA_SZ + n * ASTR + k16 * 16);
            cpa16(dst, Bt + (size_t)n * KP + kt * 32 + k16 * 8);
        }
    };

    ldgA(0); cpB(0, 0); CP_COMMIT();
    stsA(0);
    ldgA(1); cpB(1, 1); CP_COMMIT();

    const int      lrow = ((l >> 3) & 1) * 8 + (l & 7);
    const uint32_t acol = (uint32_t)((l >> 4) * 16);
    const uint32_t brow = (uint32_t)(nw + ((l >> 4) & 1) * 8 + (l & 7));
    const uint32_t bcol = (uint32_t)(((l >> 3) & 1) * 16);

    for (int kt = 0; kt < NKT; kt++) {
        CP_WAIT1();
        __syncthreads();
        if (kt + 1 < NKT) stsA((kt + 1) % 3);
        if (kt + 2 < NKT) { cpB(kt + 2, (kt + 2) % 3); ldgA(kt + 2); }
        CP_COMMIT();

        const int buf = kt % 3;
        const uint32_t sa  = sb + (uint32_t)(buf * STAGE);
        const uint32_t sbb = sa + SA_SZ;

        #pragma unroll
        for (int ks = 0; ks < 2; ks++) {
            uint32_t bb[8];
            uint32_t ba = sbb + brow * ASTR + (uint32_t)(ks * 32) + bcol;
            ldsm4(bb[0], bb[1], bb[2], bb[3], ba);
            ldsm4(bb[4], bb[5], bb[6], bb[7], ba + 16 * ASTR);
            #pragma unroll
            for (int t = 0; t < 4; t++) {
                uint32_t aa[4];
                uint32_t aadr = sa + (uint32_t)((mw + t * 16 + lrow) * ASTR + ks * 32) + acol;
                ldsm4(aa[0], aa[1], aa[2], aa[3], aadr);
                mma_f16(acc[t][0], aa, bb[0], bb[1]);
                mma_f16(acc[t][1], aa, bb[2], bb[3]);
                mma_f16(acc[t][2], aa, bb[4], bb[5]);
                mma_f16(acc[t][3], aa, bb[6], bb[7]);
            }
        }
        __syncthreads();
    }

    #pragma unroll
    for (int t = 0; t < 4; t++) {
        int r0 = bm + mw + t * 16 + (l >> 2);
        #pragma unroll
        for (int half = 0; half < 2; half++) {
            int row = r0 + half * 8;
            if (row < NND) {
                #pragma unroll
                for (int j = 0; j < 4; j++) {
                    int col = nw + j * 8 + (l & 3) * 2;
                    __half2 v = __floats2half2_rn(acc[t][j][half * 2],
                                                  acc[t][j][half * 2 + 1]);
                    *(__half2*)&C[(size_t)row * F1 + col] = v;
                }
            }
        }
    }
}

// ---------------- fusedA: agg256(h1*csrc[s]) + relu + GEMM2 -> h2 fp16 ------
__global__ __launch_bounds__(1024)
void fusedA_kernel(const __half* __restrict__ h1, const float* __restrict__ W2,
                   const float* __restrict__ b1, __half* __restrict__ h2,
                   const float* __restrict__ csrc, const float* __restrict__ cdst) {
    __shared__ float W2s[256 * 32];
    __shared__ float x1s[32][256];
    const int tid = threadIdx.x;
    for (int i = tid; i < 256 * 32; i += 1024) W2s[i] = W2[i];
    __syncthreads();

    const int wl   = tid >> 5;
    const int lane = tid & 31;
    const int node = blockIdx.x * 32 + wl;
    if (node >= NND) return;

    int i0 = g_off[node], i1 = g_off[node + 1];
    float a[8] = {0.f, 0.f, 0.f, 0.f, 0.f, 0.f, 0.f, 0.f};
    int i = i0;
    for (; i + 2 <= i1; i += 2) {
        int s0 = g_srcl[i], s1 = g_srcl[i + 1];
        float c0 = csrc[s0], c1 = csrc[s1];
        uint4 v0 = *(const uint4*)(h1 + (size_t)s0 * 256 + lane * 8);
        uint4 v1 = *(const uint4*)(h1 + (size_t)s1 * 256 + lane * 8);
        float2 f;
        f = __half22float2(*(__half2*)&v0.x); a[0] = fmaf(f.x, c0, a[0]); a[1] = fmaf(f.y, c0, a[1]);
        f = __half22float2(*(__half2*)&v0.y); a[2] = fmaf(f.x, c0, a[2]); a[3] = fmaf(f.y, c0, a[3]);
        f = __half22float2(*(__half2*)&v0.z); a[4] = fmaf(f.x, c0, a[4]); a[5] = fmaf(f.y, c0, a[5]);
        f = __half22float2(*(__half2*)&v0.w); a[6] = fmaf(f.x, c0, a[6]); a[7] = fmaf(f.y, c0, a[7]);
        f = __half22float2(*(__half2*)&v1.x); a[0] = fmaf(f.x, c1, a[0]); a[1] = fmaf(f.y, c1, a[1]);
        f = __half22float2(*(__half2*)&v1.y); a[2] = fmaf(f.x, c1, a[2]); a[3] = fmaf(f.y, c1, a[3]);
        f = __half22float2(*(__half2*)&v1.z); a[4] = fmaf(f.x, c1, a[4]); a[5] = fmaf(f.y, c1, a[5]);
        f = __half22float2(*(__half2*)&v1.w); a[6] = fmaf(f.x, c1, a[6]); a[7] = fmaf(f.y, c1, a[7]);
    }
    if (i < i1) {
        int s0 = g_srcl[i];
        float c0 = csrc[s0];
        uint4 v0 = *(const uint4*)(h1 + (size_t)s0 * 256 + lane * 8);
        float2 f;
        f = __half22float2(*(__half2*)&v0.x); a[0] = fmaf(f.x, c0, a[0]); a[1] = fmaf(f.y, c0, a[1]);
        f = __half22float2(*(__half2*)&v0.y); a[2] = fmaf(f.x, c0, a[2]); a[3] = fmaf(f.y, c0, a[3]);
        f = __half22float2(*(__half2*)&v0.z); a[4] = fmaf(f.x, c0, a[4]); a[5] = fmaf(f.y, c0, a[5]);
        f = __half22float2(*(__half2*)&v0.w); a[6] = fmaf(f.x, c0, a[6]); a[7] = fmaf(f.y, c0, a[7]);
    }
    {
        float c = cdst[node];
        const float4* bp = (const float4*)b1 + lane * 2;
        float4 b0 = bp[0], b1v = bp[1];
        float4 o0, o1;
        o0.x = fmaxf(fmaf(a[0], c, b0.x), 0.f);  o0.y = fmaxf(fmaf(a[1], c, b0.y), 0.f);
        o0.z = fmaxf(fmaf(a[2], c, b0.z), 0.f);  o0.w = fmaxf(fmaf(a[3], c, b0.w), 0.f);
        o1.x = fmaxf(fmaf(a[4], c, b1v.x), 0.f); o1.y = fmaxf(fmaf(a[5], c, b1v.y), 0.f);
        o1.z = fmaxf(fmaf(a[6], c, b1v.z), 0.f); o1.w = fmaxf(fmaf(a[7], c, b1v.w), 0.f);
        *(float4*)&x1s[wl][lane * 8]     = o0;
        *(float4*)&x1s[wl][lane * 8 + 4] = o1;
    }
    __syncwarp();
    float acc = 0.f;
    const float* xr = x1s[wl];
    #pragma unroll
    for (int k4 = 0; k4 < 64; k4++) {
        float4 x = *(const float4*)&xr[k4 * 4];
        int k = k4 * 4;
        acc = fmaf(x.x, W2s[(k + 0) * 32 + lane], acc);
        acc = fmaf(x.y, W2s[(k + 1) * 32 + lane], acc);
        acc = fmaf(x.z, W2s[(k + 2) * 32 + lane], acc);
        acc = fmaf(x.w, W2s[(k + 3) * 32 + lane], acc);
    }
    h2[(size_t)node * 32 + lane] = __float2half_rn(acc * csrc[node]);
}

// ---------------- fusedB: agg32(h2 fp16) + relu + GEMM3 -> h3 ---------------
__global__ __launch_bounds__(256)
void fusedB_kernel(const __half* __restrict__ h2, const float* __restrict__ W3,
                   const float* __restrict__ b2, float* __restrict__ h3,
                   const float* __restrict__ csrc, const float* __restrict__ cdst) {
    __shared__ float W3s[224];
    const int tid = threadIdx.x;
    if (tid < 224) W3s[tid] = W3[tid];
    __syncthreads();
    const int lane = tid & 31;
    const int node = (blockIdx.x * 256 + tid) >> 5;
    if (node >= NND) return;
    int i0 = g_off[node], i1 = g_off[node + 1];
    float a0 = 0.f, a1 = 0.f, a2 = 0.f, a3 = 0.f;
    int i = i0;
    for (; i + 4 <= i1; i += 4) {
        a0 += __half2float(h2[(size_t)g_srcl[i]     * 32 + lane]);
        a1 += __half2float(h2[(size_t)g_srcl[i + 1] * 32 + lane]);
        a2 += __half2float(h2[(size_t)g_srcl[i + 2] * 32 + lane]);
        a3 += __half2float(h2[(size_t)g_srcl[i + 3] * 32 + lane]);
    }
    for (; i < i1; i++) a0 += __half2float(h2[(size_t)g_srcl[i] * 32 + lane]);
    float x2 = fmaxf(fmaf((a0 + a1) + (a2 + a3), cdst[node], b2[lane]), 0.f);
    float s = csrc[node];
    float r[7];
    #pragma unroll
    for (int j = 0; j < 7; j++) {
        float v = x2 * W3s[lane * 7 + j];
        #pragma unroll
        for (int d = 16; d > 0; d >>= 1)
            v += __shfl_xor_sync(0xFFFFFFFFu, v, d);
        r[j] = v;
    }
    float outv = 0.f;
    #pragma unroll
    for (int j = 0; j < 7; j++) if (lane == j) outv = r[j];
    if (lane < 7) h3[(size_t)node * 8 + lane] = outv * s;
}

// ---------------- CSR aggregation F=7 + log_softmax -------------------------
__global__ __launch_bounds__(256)
void agg7_final_kernel(const float* __restrict__ h, const float* __restrict__ b3,
                       const float* __restrict__ cdst, float* __restrict__ out) {
    int warp = (blockIdx.x * blockDim.x + threadIdx.x) >> 5;
    int lane = threadIdx.x & 31;
    int sub  = lane & 7;
    int node = warp * 4 + (lane >> 3);
    if (node >= NND) return;
    int i0 = g_off[node], i1 = g_off[node + 1];
    float a = 0.f;
    if (sub < 7)
        for (int i = i0; i < i1; i++) a += h[(size_t)g_srcl[i] * 8 + sub];
    float v = (sub < 7) ? fmaf(a, cdst[node], b3[sub]) : -1e30f;
    float mx = v;
    #pragma unroll
    for (int d = 1; d < 8; d <<= 1)
        mx = fmaxf(mx, __shfl_xor_sync(0xFFFFFFFFu, mx, d));
    float e = (sub < 7) ? expf(v - mx) : 0.f;
    float se = e;
    #pragma unroll
    for (int d = 1; d < 8; d <<= 1)
        se += __shfl_xor_sync(0xFFFFFFFFu, se, d);
    float lse = logf(se);
    if (sub < 7) out[(size_t)node * 7 + sub] = v - mx - lse;
}

// ---------------- host ------------------------------------------------------
extern "C" void kernel_launch(void* const* d_in, const int* in_sizes, int n_in,
                              void* d_out, int out_size) {
    const float* feat = (const float*)d_in[0];
    const void*  edge = d_in[1];
    const float* W1   = (const float*)d_in[2];
    const float* b1   = (const float*)d_in[3];
    const float* W2   = (const float*)d_in[4];
    const float* b2   = (const float*)d_in[5];
    const float* W3   = (const float*)d_in[6];
    const float* b3   = (const float*)d_in[7];
    float* out = (float*)d_out;

    float *p_csrc, *p_cdst, *p_h3;
    __half *p_h1, *p_h2, *p_Bt;
    cudaGetSymbolAddress((void**)&p_csrc, g_csrc);
    cudaGetSymbolAddress((void**)&p_cdst, g_cdst);
    cudaGetSymbolAddress((void**)&p_h1,   g_h1);
    cudaGetSymbolAddress((void**)&p_h2,   g_h2);
    cudaGetSymbolAddress((void**)&p_h3,   g_h3);
    cudaGetSymbolAddress((void**)&p_Bt,   g_Bt);

    static int inited = 0;
    static cudaStream_t s2;
    static cudaEvent_t evFork, evJoin;
    if (!inited) {
        cudaFuncSetAttribute(gemm1_f16, cudaFuncAttributeMaxDynamicSharedMemorySize, SMEM_G1);
        cudaStreamCreateWithFlags(&s2, cudaStreamNonBlocking);
        cudaEventCreateWithFlags(&evFork, cudaEventDisableTiming);
        cudaEventCreateWithFlags(&evJoin, cudaEventDisableTiming);
        inited = 1;
    }

    // main stream: init (W1 conversion + degree zero + detect)
    init_kernel<<<(F1 * KP + 255) / 256, 256>>>(edge, W1);
    // fork: graph prep runs concurrent with gemm1
    cudaEventRecord(evFork, 0);
    cudaStreamWaitEvent(s2, evFork, 0);
    deg_kernel<<<1024, 256, 0, s2>>>(edge);
    scanA_kernel<<<NBS, 256, 0, s2>>>();
    scanC_kernel<<<NBS, 256, 0, s2>>>();
    fill_kernel<<<1024, 256, 0, s2>>>(edge);
    cudaEventRecord(evJoin, s2);

    // main stream: gemm1 (independent of graph prep now)
    gemm1_f16<<<(NND + 127) / 128, 512, SMEM_G1>>>(feat, p_Bt, p_h1);

    // join, then fused tail
    cudaStreamWaitEvent(0, evJoin, 0);
    fusedA_kernel<<<(NND + 31) / 32, 1024>>>(p_h1, W2, b1, p_h2, p_csrc, p_cdst);
    fusedB_kernel<<<(NND * 32 + 255) / 256, 256>>>(p_h2, W3, b2, p_h3, p_csrc, p_cdst);
    agg7_final_kernel<<<((NND + 3) / 4 * 32 + 255) / 256, 256>>>(p_h3, b3, p_cdst, out);
}